// round 12
// baseline (speedup 1.0000x reference)
#include <cuda_runtime.h>
#include <cuda_fp16.h>
#include <math.h>
#include <stdint.h>

#define BATCH 25
#define SEQT  600
#define EMBD  300
#define HID   512
#define G3    1536              // 3*HID
#define MROWS (BATCH*SEQT)      // 15000
#define KP    304               // padded K for input GEMM (19 x 16)

#define WSTR  520               // smem fp16 row stride (conflict-free)
#define HROWS 26                // 25 batches + 1 zero row
#define PSZ   (4*40*33)         // one ps buffer (floats)

// ---------------- scratch (device globals; no allocation allowed) ----------
__device__ float g_xg[(size_t)MROWS * G3];   // xg0 (layer-0 input gates)
__device__ __half g_ahi[(size_t)MROWS * KP]; // emb-gathered A, fp16 hi
__device__ __half g_alo[(size_t)MROWS * KP]; // fp16 lo (residual)
__device__ __half g_whi[(size_t)G3 * KP];    // w_ih0 fp16 hi
__device__ __half g_wlo[(size_t)G3 * KP];    // w_ih0 fp16 lo
__device__ __half g_h0[2][BATCH * HID];      // fp16 h transport (|h|<1)
__device__ __half g_h1[2][BATCH * HID];
__device__ float g_h0f[BATCH * HID];
__device__ float g_h1f[BATCH * HID];
__device__ unsigned g_ctr;                   // monotonic barrier counter
__device__ unsigned g_done;                  // completion counter (self-reset)

// ---------------- ptx helpers ----------------------------------------------
__device__ __forceinline__ void red_release_add(unsigned* p, unsigned v) {
    asm volatile("red.release.gpu.global.add.u32 [%0], %1;"
                 :: "l"(p), "r"(v) : "memory");
}
__device__ __forceinline__ unsigned ld_acquire(unsigned* p) {
    unsigned v;
    asm volatile("ld.acquire.gpu.global.u32 %0, [%1];"
                 : "=r"(v) : "l"(p) : "memory");
    return v;
}
__device__ __forceinline__ uint32_t smem_u32(const void* p) {
    uint32_t a;
    asm("{ .reg .u64 t; cvta.to.shared.u64 t, %1; cvt.u32.u64 %0, t; }"
        : "=r"(a) : "l"(p));
    return a;
}
__device__ __forceinline__ void ldm_x4(uint32_t* r, uint32_t addr) {
    asm volatile("ldmatrix.sync.aligned.m8n8.x4.shared.b16 {%0,%1,%2,%3}, [%4];"
                 : "=r"(r[0]), "=r"(r[1]), "=r"(r[2]), "=r"(r[3])
                 : "r"(addr));
}
__device__ __forceinline__ void mma_fp16(float* d, const uint32_t* a,
                                         uint32_t b0, uint32_t b1) {
    asm volatile(
        "mma.sync.aligned.m16n8k16.row.col.f32.f16.f16.f32 "
        "{%0,%1,%2,%3}, {%4,%5,%6,%7}, {%8,%9}, {%0,%1,%2,%3};"
        : "+f"(d[0]), "+f"(d[1]), "+f"(d[2]), "+f"(d[3])
        : "r"(a[0]), "r"(a[1]), "r"(a[2]), "r"(a[3]), "r"(b0), "r"(b1));
}
__device__ __forceinline__ float fast_sig(float x) {
    return __fdividef(1.f, 1.f + __expf(-x));
}
__device__ __forceinline__ float fast_tanh(float x) {
    return 1.f - __fdividef(2.f, __expf(2.f * x) + 1.f);
}

// ---------------- convert kernels: fp32 -> fp16 hi/lo (padded K) ------------
__global__ void cvtA_kernel(const int* __restrict__ words,
                            const float* __restrict__ emb)
{
    const int row = blockIdx.x;
    const int k   = threadIdx.x;
    const int w   = words[row];
    const float v = (k < EMBD) ? emb[(size_t)w * EMBD + k] : 0.f;
    const __half h = __float2half_rn(v);
    g_ahi[(size_t)row * KP + k] = h;
    g_alo[(size_t)row * KP + k] = __float2half_rn(v - __half2float(h));
}

__global__ void cvtW_kernel(const float* __restrict__ w_ih0)
{
    const int row = blockIdx.x;
    const int k   = threadIdx.x;
    const float v = (k < EMBD) ? w_ih0[(size_t)row * EMBD + k] : 0.f;
    const __half h = __float2half_rn(v);
    g_whi[(size_t)row * KP + k] = h;
    g_wlo[(size_t)row * KP + k] = __float2half_rn(v - __half2float(h));
}

// ---------------- tensor-core input GEMM (fp16 hi/lo, 3 terms) --------------
#define ASTR 24
__global__ __launch_bounds__(256) void gemm_tc_kernel(
    const float* __restrict__ bias)
{
    __shared__ __half sah[128 * ASTR], sal[128 * ASTR];
    __shared__ __half swh[128 * ASTR], swl[128 * ASTR];

    const int tid  = threadIdx.x;
    const int wid  = tid >> 5;
    const int lane = tid & 31;
    const int m0   = blockIdx.y * 128;
    const int n0   = blockIdx.x * 128;
    const int mw   = wid & 3;
    const int nw   = wid >> 2;

    uint32_t abh[2], abl[2];
    {
        const int t = lane >> 3, ir = lane & 7;
        const int ac = (t >> 1) * 8;
#pragma unroll
        for (int mt = 0; mt < 2; mt++) {
            const int ar = mw * 32 + mt * 16 + (t & 1) * 8 + ir;
            const uint32_t off = (uint32_t)(ar * ASTR + ac) * 2u;
            abh[mt] = smem_u32(sah) + off;
            abl[mt] = smem_u32(sal) + off;
        }
    }
    const int bbase = (nw * 64 + (lane >> 2)) * ASTR + (lane & 3) * 2;

    float D[2][8][4];
#pragma unroll
    for (int mt = 0; mt < 2; mt++)
#pragma unroll
        for (int j = 0; j < 8; j++)
#pragma unroll
            for (int e = 0; e < 4; e++) D[mt][j][e] = 0.f;

    const int arow  = tid >> 1;
    const int ahalf = tid & 1;
    const bool aok  = (m0 + arow) < MROWS;
    const __half* agh = g_ahi + (size_t)(m0 + arow) * KP + ahalf * 8;
    const __half* agl = g_alo + (size_t)(m0 + arow) * KP + ahalf * 8;
    const __half* wgh = g_whi + (size_t)(n0 + arow) * KP + ahalf * 8;
    const __half* wgl = g_wlo + (size_t)(n0 + arow) * KP + ahalf * 8;
    __half* dah = sah + arow * ASTR + ahalf * 8;
    __half* dal = sal + arow * ASTR + ahalf * 8;
    __half* dwh = swh + arow * ASTR + ahalf * 8;
    __half* dwl = swl + arow * ASTR + ahalf * 8;

    for (int it = 0; it < KP / 16; it++) {
        const int k0 = it * 16;
        if (aok) {
            *(uint4*)dah = *(const uint4*)(agh + k0);
            *(uint4*)dal = *(const uint4*)(agl + k0);
        }
        *(uint4*)dwh = *(const uint4*)(wgh + k0);
        *(uint4*)dwl = *(const uint4*)(wgl + k0);
        __syncthreads();

        uint32_t ah[2][4], al[2][4];
        ldm_x4(ah[0], abh[0]); ldm_x4(ah[1], abh[1]);
        ldm_x4(al[0], abl[0]); ldm_x4(al[1], abl[1]);
#pragma unroll
        for (int j = 0; j < 8; j++) {
            const int bo = bbase + j * 8 * ASTR;
            const uint32_t bh0 = *(const uint32_t*)(swh + bo);
            const uint32_t bh1 = *(const uint32_t*)(swh + bo + 8);
            const uint32_t bl0 = *(const uint32_t*)(swl + bo);
            const uint32_t bl1 = *(const uint32_t*)(swl + bo + 8);
#pragma unroll
            for (int mt = 0; mt < 2; mt++) {
                mma_fp16(D[mt][j], ah[mt], bh0, bh1);
                mma_fp16(D[mt][j], ah[mt], bl0, bl1);
                mma_fp16(D[mt][j], al[mt], bh0, bh1);
            }
        }
        __syncthreads();
    }

    const int rb = m0 + mw * 32 + (lane >> 2);
    const int cb = n0 + nw * 64 + (lane & 3) * 2;
#pragma unroll
    for (int j = 0; j < 8; j++) {
        const int c = cb + j * 8;
        const float b0v = bias[c], b1v = bias[c + 1];
#pragma unroll
        for (int mt = 0; mt < 2; mt++) {
            const int r0 = rb + mt * 16;
            if (r0 < MROWS) {
                g_xg[(size_t)r0 * G3 + c    ] = D[mt][j][0] + b0v;
                g_xg[(size_t)r0 * G3 + c + 1] = D[mt][j][1] + b1v;
            }
            if (r0 + 8 < MROWS) {
                g_xg[(size_t)(r0 + 8) * G3 + c    ] = D[mt][j][2] + b0v;
                g_xg[(size_t)(r0 + 8) * G3 + c + 1] = D[mt][j][3] + b1v;
            }
        }
    }
}

// ---------------- fused two-layer GRU: 1 sync/step, per-warp grid barrier ---
// 128 blocks; block q owns units [4q,4q+4) of both layers; weights (smem,
// fp16 hi/lo) rows: 0-11 hh0, 12-23 ih1, 24-35 hh1, 36-39 zero pad.
// ps is double-buffered (parity s&1) so only ONE block sync per step; each
// warp arrives/polls the grid barrier independently (8 arrivals per block).
__global__ __launch_bounds__(256, 1) void gru_fused_kernel(
    const float* __restrict__ w_hh0, const float* __restrict__ b_hh0,
    const float* __restrict__ w_ih1, const float* __restrict__ b_ih1,
    const float* __restrict__ w_hh1, const float* __restrict__ b_hh1,
    const float* __restrict__ hinit)  // [2][25][512]
{
    extern __shared__ __half smh[];
    __half* sh0 = smh;                         // [26][520]
    __half* sh1 = sh0 + HROWS * WSTR;          // [26][520]
    __half* whi = sh1 + HROWS * WSTR;          // [40][520]
    __half* wlo = whi + 40 * WSTR;             // [40][520]
    float* ps = (float*)(wlo + 40 * WSTR);     // [2][4][40][33] double-buffered
    float* bs = ps + 2 * PSZ;                  // [36]

    const int tid  = threadIdx.x;
    const int wid  = tid >> 5;
    const int lane = tid & 31;
    const int u0   = blockIdx.x * 4;
    const int mt   = wid & 1;          // m-tile (batch 0-15 / 16-31)
    const int kw   = wid >> 1;         // k-slice index
    const int kb   = kw * 128;         // k base (fp16 elems)

    const float* hinit0 = hinit;
    const float* hinit1 = hinit + BATCH * HID;

    // ---- prologue: weight split into fp16 hi/lo, pad rows, biases ---------
    {
        const float* mats[3] = { w_hh0, w_ih1, w_hh1 };
        for (int i = tid; i < 36 * 128; i += 256) {
            const int j  = i >> 7;
            const int kq = (i & 127) << 2;
            const int m  = j / 12;
            const int r  = j % 12;
            const int grow = (r >> 2) * HID + u0 + (r & 3);
            float4 v = *(const float4*)(mats[m] + (size_t)grow * HID + kq);
            const int o = j * WSTR + kq;
            float vv[4] = { v.x, v.y, v.z, v.w };
#pragma unroll
            for (int e = 0; e < 4; e++) {
                __half h = __float2half_rn(vv[e]);
                whi[o + e] = h;
                wlo[o + e] = __float2half_rn(vv[e] - __half2float(h));
            }
        }
        for (int i = tid; i < 4 * WSTR; i += 256) {          // rows 36-39 = 0
            whi[36 * WSTR + i] = __float2half_rn(0.f);
            wlo[36 * WSTR + i] = __float2half_rn(0.f);
        }
        for (int i = tid; i < WSTR; i += 256) {              // h row 25 = 0
            sh0[25 * WSTR + i] = __float2half_rn(0.f);
            sh1[25 * WSTR + i] = __float2half_rn(0.f);
        }
        if (tid < 36) {
            const int m = tid / 12, r = tid % 12;
            const float* bp = (m == 0) ? b_hh0 : (m == 1) ? b_ih1 : b_hh1;
            bs[tid] = bp[(r >> 2) * HID + u0 + (r & 3)];
        }
    }

    // gate-thread identities + exact fp32 h_old in registers
    const int gb0 = tid >> 2, gu0 = tid & 3;
    const int tl  = tid - 128;
    const int gb1 = tl >> 2,  gu1 = tl & 3;
    float h0old = 0.f, h1old = 0.f;
    if (tid < 100)               h0old = hinit0[gb0 * HID + u0 + gu0];
    if (tid >= 128 && tid < 228) h1old = hinit1[gb1 * HID + u0 + gu1];
    float stR = 0.f, stZ = 0.f, stN = 0.f;   // gx1 sums carried one step

    // ldmatrix lane addressing (A = h, m16k16 tiles)
    uint32_t lb0, lb1;
    {
        const int t  = lane >> 3;
        const int ir = lane & 7;
        int arow = mt * 16 + (t & 1) * 8 + ir;
        if (arow > 25) arow = 25;                       // zeroed pad row
        const int acol = (t >> 1) * 8;
        const uint32_t aoff = (uint32_t)(arow * WSTR + kb + acol) * 2u;
        lb0 = smem_u32(sh0) + aoff;
        lb1 = smem_u32(sh1) + aoff;
    }
    const int wbase = (lane >> 2) * WSTR + ((lane & 3) << 1) + kb;

    const int r0 = mt ? 16 : 0;
    const int nr = mt ? 9  : 16;     // rows this warp stages

    __syncthreads();

    // ---- prime xg for step 0
    float xr0 = 0.f, xz0 = 0.f, xn0 = 0.f;
    if (tid < 100) {
        const float* xrow = g_xg + (size_t)gb0 * SEQT * G3 + u0 + gu0;
        xr0 = __ldcg(xrow);
        xz0 = __ldcg(xrow + HID);
        xn0 = __ldcg(xrow + 2 * HID);
    }

    for (int s = 0; s <= SEQT + 1; s++) {
        float* psb = ps + (s & 1) * PSZ;

        // ---- warp-local staging of h0[s-1], h1[s-3] (fp16)
        if (s == 0) {
            for (int i = lane; i < nr * 32; i += 32) {
                const int r = r0 + (i >> 5), q = i & 31;
                float4 v = __ldcg((const float4*)(hinit0 + r * HID + kb) + q);
                const int o = r * WSTR + kb + q * 4;
                sh0[o + 0] = __float2half_rn(v.x);
                sh0[o + 1] = __float2half_rn(v.y);
                sh0[o + 2] = __float2half_rn(v.z);
                sh0[o + 3] = __float2half_rn(v.w);
            }
        } else {
            const __half* s0 = g_h0[(s - 1) & 1];
            for (int i = lane; i < nr * 16; i += 32) {
                const int r = r0 + (i >> 4), q = i & 15;
                float4 vh = __ldcg((const float4*)(s0 + r * HID + kb) + q);
                *((float4*)(sh0 + r * WSTR + kb) + q) = vh;
            }
        }
        if (s <= 2) {
            for (int i = lane; i < nr * 32; i += 32) {
                const int r = r0 + (i >> 5), q = i & 31;
                float4 v = __ldcg((const float4*)(hinit1 + r * HID + kb) + q);
                const int o = r * WSTR + kb + q * 4;
                sh1[o + 0] = __float2half_rn(v.x);
                sh1[o + 1] = __float2half_rn(v.y);
                sh1[o + 2] = __float2half_rn(v.z);
                sh1[o + 3] = __float2half_rn(v.w);
            }
        } else {
            const __half* s1 = g_h1[(s - 1) & 1];
            for (int i = lane; i < nr * 16; i += 32) {
                const int r = r0 + (i >> 4), q = i & 15;
                float4 vh = __ldcg((const float4*)(s1 + r * HID + kb) + q);
                *((float4*)(sh1 + r * WSTR + kb) + q) = vh;
            }
        }
        __syncwarp();

        // ---- MMA pass: D[m16][n8 x5] over this warp's 128-wide k-slice
        float D[5][4];
#pragma unroll
        for (int n = 0; n < 5; n++)
#pragma unroll
            for (int e = 0; e < 4; e++) D[n][e] = 0.f;

#pragma unroll
        for (int ks = 0; ks < 8; ks++) {
            uint32_t a0[4], a1[4];
            ldm_x4(a0, lb0 + ks * 32);
            ldm_x4(a1, lb1 + ks * 32);
            const int wi = wbase + ks * 16;
#pragma unroll
            for (int nt = 0; nt < 5; nt++) {
                const int idx = wi + nt * 8 * WSTR;
                const uint32_t b0h = *(const uint32_t*)(whi + idx);
                const uint32_t b1h = *(const uint32_t*)(whi + idx + 8);
                const uint32_t b0l = *(const uint32_t*)(wlo + idx);
                const uint32_t b1l = *(const uint32_t*)(wlo + idx + 8);
                const uint32_t* A = (nt < 3) ? a0 : a1;
                mma_fp16(D[nt], A, b0h, b1h);   // h . Whi
                mma_fp16(D[nt], A, b0l, b1l);   // h . Wlo
            }
        }

        // ---- dump D frags to psb[kw][row40][batch33]
        {
            const int c2 = (lane & 3) << 1;
            const int b  = mt * 16 + (lane >> 2);
#pragma unroll
            for (int nt = 0; nt < 5; nt++) {
                const int col = nt * 8 + c2;
                psb[(kw * 40 + col    ) * 33 + b    ] = D[nt][0];
                psb[(kw * 40 + col + 1) * 33 + b    ] = D[nt][1];
                psb[(kw * 40 + col    ) * 33 + b + 8] = D[nt][2];
                psb[(kw * 40 + col + 1) * 33 + b + 8] = D[nt][3];
            }
        }
        __syncthreads();   // the ONLY block-wide sync per step

        // ---- layer-0 gates: t = s (threads 0..99)
        if (tid < 100 && s < SEQT) {
            const int u = u0 + gu0;
            float gr_ = bs[gu0], gz_ = bs[4 + gu0], gn_ = bs[8 + gu0];
#pragma unroll
            for (int k = 0; k < 4; k++) {
                gr_ += psb[(k * 40 +     gu0) * 33 + gb0];
                gz_ += psb[(k * 40 + 4 + gu0) * 33 + gb0];
                gn_ += psb[(k * 40 + 8 + gu0) * 33 + gb0];
            }
            const float r = fast_sig(xr0 + gr_);
            const float z = fast_sig(xz0 + gz_);
            const float n = fast_tanh(xn0 + r * gn_);
            const float hn = (1.f - z) * n + z * h0old;
            h0old = hn;
            g_h0[s & 1][gb0 * HID + u] = __float2half_rn(hn);
            if (s == SEQT - 1) g_h0f[gb0 * HID + u] = hn;
        }

        // ---- layer-1 gates: t = s-2 (threads 128..227); stash gx1 for s+1
        if (tid >= 128 && tid < 228) {
            const int u = u0 + gu1;
            float nR = 0.f, nZ = 0.f, nN = 0.f;
            float hr = bs[24 + gu1], hz = bs[28 + gu1], hn_ = bs[32 + gu1];
#pragma unroll
            for (int k = 0; k < 4; k++) {
                nR  += psb[(k * 40 + 12 + gu1) * 33 + gb1];
                nZ  += psb[(k * 40 + 16 + gu1) * 33 + gb1];
                nN  += psb[(k * 40 + 20 + gu1) * 33 + gb1];
                hr  += psb[(k * 40 + 24 + gu1) * 33 + gb1];
                hz  += psb[(k * 40 + 28 + gu1) * 33 + gb1];
                hn_ += psb[(k * 40 + 32 + gu1) * 33 + gb1];
            }
            if (s >= 2) {
                const float xr = bs[12 + gu1] + stR;
                const float xz = bs[16 + gu1] + stZ;
                const float xn = bs[20 + gu1] + stN;
                const float r = fast_sig(xr + hr);
                const float z = fast_sig(xz + hz);
                const float n = fast_tanh(xn + r * hn_);
                const float hnew = (1.f - z) * n + z * h1old;
                h1old = hnew;
                g_h1[s & 1][gb1 * HID + u] = __float2half_rn(hnew);
                if (s == SEQT + 1) g_h1f[gb1 * HID + u] = hnew;
            }
            stR = nR; stZ = nZ; stN = nN;
        }

        // ---- per-warp barrier: arrive, shadow xg prefetch, poll ------------
        if (s < SEQT + 1) {
            __syncwarp();          // warp's gate stores done (cumulativity)
            if (lane == 0) red_release_add(&g_ctr, 1u);

            // shadow prefetch: xg for step s+1 (step-indexed, barrier-free)
            if (tid < 100 && (s + 1) < SEQT) {
                const float* xrow =
                    g_xg + ((size_t)gb0 * SEQT + (s + 1)) * G3 + u0 + gu0;
                xr0 = __ldcg(xrow);
                xz0 = __ldcg(xrow + HID);
                xn0 = __ldcg(xrow + 2 * HID);
            }

            const unsigned target = (unsigned)(s + 1) * 1024u;  // 128 blk x 8
            if (lane == 0) {
                while (ld_acquire(&g_ctr) < target) { }
            }
            __syncwarp();
        }
    }

    // ---- self-reset: last WARP to finish zeroes the counters --------------
    if (lane == 0) {
        const unsigned old = atomicAdd(&g_done, 1u);
        if (old == 1023u) {
            atomicExch(&g_ctr, 0u);
            atomicExch(&g_done, 0u);
        }
    }
}

// ---------------- finalize: sig = sigmoid(h1_final . fc_w + fc_b); pack out --
__global__ void finalize_kernel(const float* __restrict__ fc_w,
                                const float* __restrict__ fc_b,
                                float* __restrict__ out)
{
    if (blockIdx.x < 100) {
        const int idx = blockIdx.x * 256 + threadIdx.x;     // 0..25599
        const float v = (idx < BATCH * HID) ? g_h0f[idx]
                                            : g_h1f[idx - BATCH * HID];
        out[25 + idx] = v;
    } else {
        const int b = threadIdx.x;
        if (b < BATCH) {
            float s = fc_b[0];
            for (int k = 0; k < HID; k++)
                s += g_h1f[b * HID + k] * fc_w[k];
            out[b] = 1.f / (1.f + expf(-s));
        }
    }
}

// ---------------- launch ----------------------------------------------------
extern "C" void kernel_launch(void* const* d_in, const int* in_sizes, int n_in,
                              void* d_out, int out_size)
{
    const int*   words  = (const int*)  d_in[0];
    const float* hidden = (const float*)d_in[1];
    const float* emb    = (const float*)d_in[2];
    const float* w_ih0  = (const float*)d_in[3];
    const float* w_hh0  = (const float*)d_in[4];
    const float* b_ih0  = (const float*)d_in[5];
    const float* b_hh0  = (const float*)d_in[6];
    const float* w_ih1  = (const float*)d_in[7];
    const float* w_hh1  = (const float*)d_in[8];
    const float* b_ih1  = (const float*)d_in[9];
    const float* b_hh1  = (const float*)d_in[10];
    const float* fc_w   = (const float*)d_in[11];
    const float* fc_b   = (const float*)d_in[12];
    float* out = (float*)d_out;

    const size_t smem_bytes =
        (size_t)(2 * HROWS * WSTR + 2 * 40 * WSTR) * sizeof(__half)
        + (size_t)(2 * PSZ + 64) * sizeof(float);
    cudaFuncSetAttribute(gru_fused_kernel,
                         cudaFuncAttributeMaxDynamicSharedMemorySize,
                         (int)smem_bytes);

    // 5-launch pattern; capture idx 3 = gru_fused_kernel
    cvtA_kernel<<<MROWS, KP>>>(words, emb);                          // 0
    cvtW_kernel<<<G3, KP>>>(w_ih0);                                  // 1
    gemm_tc_kernel<<<dim3(G3 / 128, (MROWS + 127) / 128), 256>>>(    // 2
        b_ih0);
    gru_fused_kernel<<<128, 256, smem_bytes>>>(                      // 3
        w_hh0, b_hh0, w_ih1, b_ih1, w_hh1, b_hh1, hidden);
    finalize_kernel<<<101, 256>>>(fc_w, fc_b, out);                  // 4
}

// round 13
// speedup vs baseline: 1.2011x; 1.2011x over previous
#include <cuda_runtime.h>
#include <cuda_fp16.h>
#include <math.h>
#include <stdint.h>

#define BATCH 25
#define SEQT  600
#define EMBD  300
#define HID   512
#define G3    1536              // 3*HID
#define MROWS (BATCH*SEQT)      // 15000
#define KP    304               // padded K for input GEMM (19 x 16)

#define WSTR  520               // smem fp16 row stride (conflict-free)
#define HROWS 26                // 25 batches + 1 zero row
#define NBLK  64                // GRU grid (8 units per block)
#define NROW  72                // weight rows: 24 hh0 | 24 ih1 | 24 hh1
#define NTILE 9                 // 72 / 8 n-tiles

// ---------------- scratch (device globals; no allocation allowed) ----------
__device__ float g_xg[(size_t)MROWS * G3];   // xg0 (layer-0 input gates)
__device__ __half g_ahi[(size_t)MROWS * KP]; // emb-gathered A, fp16 hi
__device__ __half g_alo[(size_t)MROWS * KP]; // fp16 lo (residual)
__device__ __half g_whi[(size_t)G3 * KP];    // w_ih0 fp16 hi
__device__ __half g_wlo[(size_t)G3 * KP];    // w_ih0 fp16 lo
__device__ __half g_h0[2][BATCH * HID];      // fp16 h transport (|h|<1)
__device__ __half g_h1[2][BATCH * HID];
__device__ float g_h0f[BATCH * HID];
__device__ float g_h1f[BATCH * HID];
__device__ unsigned g_ctr;                   // monotonic barrier counter
__device__ unsigned g_done;                  // completion counter (self-reset)

// ---------------- ptx helpers ----------------------------------------------
__device__ __forceinline__ void red_release_add(unsigned* p, unsigned v) {
    asm volatile("red.release.gpu.global.add.u32 [%0], %1;"
                 :: "l"(p), "r"(v) : "memory");
}
__device__ __forceinline__ unsigned ld_acquire(unsigned* p) {
    unsigned v;
    asm volatile("ld.acquire.gpu.global.u32 %0, [%1];"
                 : "=r"(v) : "l"(p) : "memory");
    return v;
}
__device__ __forceinline__ uint32_t smem_u32(const void* p) {
    uint32_t a;
    asm("{ .reg .u64 t; cvta.to.shared.u64 t, %1; cvt.u32.u64 %0, t; }"
        : "=r"(a) : "l"(p));
    return a;
}
__device__ __forceinline__ void ldm_x4(uint32_t* r, uint32_t addr) {
    asm volatile("ldmatrix.sync.aligned.m8n8.x4.shared.b16 {%0,%1,%2,%3}, [%4];"
                 : "=r"(r[0]), "=r"(r[1]), "=r"(r[2]), "=r"(r[3])
                 : "r"(addr));
}
__device__ __forceinline__ void mma_fp16(float* d, const uint32_t* a,
                                         uint32_t b0, uint32_t b1) {
    asm volatile(
        "mma.sync.aligned.m16n8k16.row.col.f32.f16.f16.f32 "
        "{%0,%1,%2,%3}, {%4,%5,%6,%7}, {%8,%9}, {%0,%1,%2,%3};"
        : "+f"(d[0]), "+f"(d[1]), "+f"(d[2]), "+f"(d[3])
        : "r"(a[0]), "r"(a[1]), "r"(a[2]), "r"(a[3]), "r"(b0), "r"(b1));
}
__device__ __forceinline__ float fast_sig(float x) {
    return __fdividef(1.f, 1.f + __expf(-x));
}
__device__ __forceinline__ float fast_tanh(float x) {
    return 1.f - __fdividef(2.f, __expf(2.f * x) + 1.f);
}

// ---------------- convert kernels: fp32 -> fp16 hi/lo (padded K) ------------
__global__ void cvtA_kernel(const int* __restrict__ words,
                            const float* __restrict__ emb)
{
    const int row = blockIdx.x;
    const int k   = threadIdx.x;
    const int w   = words[row];
    const float v = (k < EMBD) ? emb[(size_t)w * EMBD + k] : 0.f;
    const __half h = __float2half_rn(v);
    g_ahi[(size_t)row * KP + k] = h;
    g_alo[(size_t)row * KP + k] = __float2half_rn(v - __half2float(h));
}

__global__ void cvtW_kernel(const float* __restrict__ w_ih0)
{
    const int row = blockIdx.x;
    const int k   = threadIdx.x;
    const float v = (k < EMBD) ? w_ih0[(size_t)row * EMBD + k] : 0.f;
    const __half h = __float2half_rn(v);
    g_whi[(size_t)row * KP + k] = h;
    g_wlo[(size_t)row * KP + k] = __float2half_rn(v - __half2float(h));
}

// ---------------- tensor-core input GEMM (fp16 hi/lo, 3 terms) --------------
#define ASTR 24
__global__ __launch_bounds__(256) void gemm_tc_kernel(
    const float* __restrict__ bias)
{
    __shared__ __half sah[128 * ASTR], sal[128 * ASTR];
    __shared__ __half swh[128 * ASTR], swl[128 * ASTR];

    const int tid  = threadIdx.x;
    const int wid  = tid >> 5;
    const int lane = tid & 31;
    const int m0   = blockIdx.y * 128;
    const int n0   = blockIdx.x * 128;
    const int mw   = wid & 3;
    const int nw   = wid >> 2;

    uint32_t abh[2], abl[2];
    {
        const int t = lane >> 3, ir = lane & 7;
        const int ac = (t >> 1) * 8;
#pragma unroll
        for (int mt = 0; mt < 2; mt++) {
            const int ar = mw * 32 + mt * 16 + (t & 1) * 8 + ir;
            const uint32_t off = (uint32_t)(ar * ASTR + ac) * 2u;
            abh[mt] = smem_u32(sah) + off;
            abl[mt] = smem_u32(sal) + off;
        }
    }
    const int bbase = (nw * 64 + (lane >> 2)) * ASTR + (lane & 3) * 2;

    float D[2][8][4];
#pragma unroll
    for (int mt = 0; mt < 2; mt++)
#pragma unroll
        for (int j = 0; j < 8; j++)
#pragma unroll
            for (int e = 0; e < 4; e++) D[mt][j][e] = 0.f;

    const int arow  = tid >> 1;
    const int ahalf = tid & 1;
    const bool aok  = (m0 + arow) < MROWS;
    const __half* agh = g_ahi + (size_t)(m0 + arow) * KP + ahalf * 8;
    const __half* agl = g_alo + (size_t)(m0 + arow) * KP + ahalf * 8;
    const __half* wgh = g_whi + (size_t)(n0 + arow) * KP + ahalf * 8;
    const __half* wgl = g_wlo + (size_t)(n0 + arow) * KP + ahalf * 8;
    __half* dah = sah + arow * ASTR + ahalf * 8;
    __half* dal = sal + arow * ASTR + ahalf * 8;
    __half* dwh = swh + arow * ASTR + ahalf * 8;
    __half* dwl = swl + arow * ASTR + ahalf * 8;

    for (int it = 0; it < KP / 16; it++) {
        const int k0 = it * 16;
        if (aok) {
            *(uint4*)dah = *(const uint4*)(agh + k0);
            *(uint4*)dal = *(const uint4*)(agl + k0);
        }
        *(uint4*)dwh = *(const uint4*)(wgh + k0);
        *(uint4*)dwl = *(const uint4*)(wgl + k0);
        __syncthreads();

        uint32_t ah[2][4], al[2][4];
        ldm_x4(ah[0], abh[0]); ldm_x4(ah[1], abh[1]);
        ldm_x4(al[0], abl[0]); ldm_x4(al[1], abl[1]);
#pragma unroll
        for (int j = 0; j < 8; j++) {
            const int bo = bbase + j * 8 * ASTR;
            const uint32_t bh0 = *(const uint32_t*)(swh + bo);
            const uint32_t bh1 = *(const uint32_t*)(swh + bo + 8);
            const uint32_t bl0 = *(const uint32_t*)(swl + bo);
            const uint32_t bl1 = *(const uint32_t*)(swl + bo + 8);
#pragma unroll
            for (int mt = 0; mt < 2; mt++) {
                mma_fp16(D[mt][j], ah[mt], bh0, bh1);
                mma_fp16(D[mt][j], ah[mt], bl0, bl1);
                mma_fp16(D[mt][j], al[mt], bh0, bh1);
            }
        }
        __syncthreads();
    }

    const int rb = m0 + mw * 32 + (lane >> 2);
    const int cb = n0 + nw * 64 + (lane & 3) * 2;
#pragma unroll
    for (int j = 0; j < 8; j++) {
        const int c = cb + j * 8;
        const float b0v = bias[c], b1v = bias[c + 1];
#pragma unroll
        for (int mt = 0; mt < 2; mt++) {
            const int r0 = rb + mt * 16;
            if (r0 < MROWS) {
                g_xg[(size_t)r0 * G3 + c    ] = D[mt][j][0] + b0v;
                g_xg[(size_t)r0 * G3 + c + 1] = D[mt][j][1] + b1v;
            }
            if (r0 + 8 < MROWS) {
                g_xg[(size_t)(r0 + 8) * G3 + c    ] = D[mt][j][2] + b0v;
                g_xg[(size_t)(r0 + 8) * G3 + c + 1] = D[mt][j][3] + b1v;
            }
        }
    }
}

// ---------------- fused two-layer GRU: 64 blocks x 8 units, W fp16 hi-only --
// Block q owns units [8q,8q+8) of both layers; 72 weight rows in smem:
// 0-23 hh0, 24-47 ih1, 48-71 hh1 (row = m*24 + g*8 + uu). 9 exact n-tiles.
// Single-term MMA (W hi only); h transport fp16; fp32 h_old in registers.
// Gate threads tid<200 process BOTH layers (b = tid>>3, uu = tid&7).
__global__ __launch_bounds__(256, 1) void gru_fused_kernel(
    const float* __restrict__ w_hh0, const float* __restrict__ b_hh0,
    const float* __restrict__ w_ih1, const float* __restrict__ b_ih1,
    const float* __restrict__ w_hh1, const float* __restrict__ b_hh1,
    const float* __restrict__ hinit)  // [2][25][512]
{
    extern __shared__ __half smh[];
    __half* sh0 = smh;                         // [26][520]
    __half* sh1 = sh0 + HROWS * WSTR;          // [26][520]
    __half* whi = sh1 + HROWS * WSTR;          // [72][520]
    float* ps = (float*)(whi + NROW * WSTR);   // [4][72][33]
    float* bs = ps + 4 * NROW * 33;            // [72]

    const int tid  = threadIdx.x;
    const int wid  = tid >> 5;
    const int lane = tid & 31;
    const int u0   = blockIdx.x * 8;
    const int mt   = wid & 1;          // m-tile (batch 0-15 / 16-31)
    const int kw   = wid >> 1;         // k-slice index
    const int kb   = kw * 128;         // k base (fp16 elems)

    const float* hinit0 = hinit;
    const float* hinit1 = hinit + BATCH * HID;

    // ---- prologue: weights (hi only), biases, zero pad h row ---------------
    {
        const float* mats[3] = { w_hh0, w_ih1, w_hh1 };
        for (int i = tid; i < NROW * 128; i += 256) {
            const int j  = i >> 7;                 // row 0..71
            const int kq = (i & 127) << 2;
            const int m  = j / 24;
            const int r  = j % 24;
            const int grow = (r >> 3) * HID + u0 + (r & 7);
            float4 v = *(const float4*)(mats[m] + (size_t)grow * HID + kq);
            const int o = j * WSTR + kq;
            whi[o + 0] = __float2half_rn(v.x);
            whi[o + 1] = __float2half_rn(v.y);
            whi[o + 2] = __float2half_rn(v.z);
            whi[o + 3] = __float2half_rn(v.w);
        }
        for (int i = tid; i < WSTR; i += 256) {              // h row 25 = 0
            sh0[25 * WSTR + i] = __float2half_rn(0.f);
            sh1[25 * WSTR + i] = __float2half_rn(0.f);
        }
        if (tid < NROW) {
            const int m = tid / 24, r = tid % 24;
            const float* bp = (m == 0) ? b_hh0 : (m == 1) ? b_ih1 : b_hh1;
            bs[tid] = bp[(r >> 3) * HID + u0 + (r & 7)];
        }
    }

    // gate-thread identities (tid<200 handles both layers)
    const int gb = tid >> 3;          // batch 0..24
    const int gu = tid & 7;           // local unit 0..7
    const int u  = u0 + gu;
    float h0old = 0.f, h1old = 0.f;
    if (tid < 200) {
        h0old = hinit0[gb * HID + u];
        h1old = hinit1[gb * HID + u];
    }
    float stR = 0.f, stZ = 0.f, stN = 0.f;   // gx1 sums carried one step

    // ldmatrix lane addressing (A = h, m16k16 tiles)
    uint32_t lb0, lb1;
    {
        const int t  = lane >> 3;
        const int ir = lane & 7;
        int arow = mt * 16 + (t & 1) * 8 + ir;
        if (arow > 25) arow = 25;                       // zeroed pad row
        const int acol = (t >> 1) * 8;
        const uint32_t aoff = (uint32_t)(arow * WSTR + kb + acol) * 2u;
        lb0 = smem_u32(sh0) + aoff;
        lb1 = smem_u32(sh1) + aoff;
    }
    const int wbase = (lane >> 2) * WSTR + ((lane & 3) << 1) + kb;

    const int r0 = mt ? 16 : 0;
    const int nr = mt ? 9  : 16;     // rows this warp stages

    __syncthreads();

    for (int s = 0; s <= SEQT + 1; s++) {
        // ---- prefetch xg0[s] (hidden under staging + MMA)
        float xr0 = 0.f, xz0 = 0.f, xn0 = 0.f;
        if (tid < 200 && s < SEQT) {
            const float* xrow = g_xg + ((size_t)gb * SEQT + s) * G3;
            xr0 = __ldcg(xrow + u);
            xz0 = __ldcg(xrow + HID + u);
            xn0 = __ldcg(xrow + 2 * HID + u);
        }

        // ---- warp-local staging of h0[s-1], h1[s-3] (fp16)
        if (s == 0) {
            for (int i = lane; i < nr * 32; i += 32) {
                const int r = r0 + (i >> 5), q = i & 31;
                float4 v = __ldcg((const float4*)(hinit0 + r * HID + kb) + q);
                const int o = r * WSTR + kb + q * 4;
                sh0[o + 0] = __float2half_rn(v.x);
                sh0[o + 1] = __float2half_rn(v.y);
                sh0[o + 2] = __float2half_rn(v.z);
                sh0[o + 3] = __float2half_rn(v.w);
            }
        } else {
            const __half* s0 = g_h0[(s - 1) & 1];
            for (int i = lane; i < nr * 16; i += 32) {
                const int r = r0 + (i >> 4), q = i & 15;
                float4 vh = __ldcg((const float4*)(s0 + r * HID + kb) + q);
                *((float4*)(sh0 + r * WSTR + kb) + q) = vh;
            }
        }
        if (s <= 2) {
            for (int i = lane; i < nr * 32; i += 32) {
                const int r = r0 + (i >> 5), q = i & 31;
                float4 v = __ldcg((const float4*)(hinit1 + r * HID + kb) + q);
                const int o = r * WSTR + kb + q * 4;
                sh1[o + 0] = __float2half_rn(v.x);
                sh1[o + 1] = __float2half_rn(v.y);
                sh1[o + 2] = __float2half_rn(v.z);
                sh1[o + 3] = __float2half_rn(v.w);
            }
        } else {
            const __half* s1 = g_h1[(s - 1) & 1];
            for (int i = lane; i < nr * 16; i += 32) {
                const int r = r0 + (i >> 4), q = i & 15;
                float4 vh = __ldcg((const float4*)(s1 + r * HID + kb) + q);
                *((float4*)(sh1 + r * WSTR + kb) + q) = vh;
            }
        }
        __syncwarp();

        // ---- MMA pass: D[m16][n8 x9]; single term (W hi only)
        float D[NTILE][4];
#pragma unroll
        for (int n = 0; n < NTILE; n++)
#pragma unroll
            for (int e = 0; e < 4; e++) D[n][e] = 0.f;

#pragma unroll
        for (int ks = 0; ks < 8; ks++) {
            uint32_t a0[4], a1[4];
            ldm_x4(a0, lb0 + ks * 32);
            ldm_x4(a1, lb1 + ks * 32);
            const int wi = wbase + ks * 16;
#pragma unroll
            for (int nt = 0; nt < NTILE; nt++) {
                const int idx = wi + nt * 8 * WSTR;
                const uint32_t b0 = *(const uint32_t*)(whi + idx);
                const uint32_t b1 = *(const uint32_t*)(whi + idx + 8);
                const uint32_t* A = (nt < 6) ? a0 : a1;
                mma_fp16(D[nt], A, b0, b1);
            }
        }

        // ---- dump D frags to ps[kw][row72][batch33]
        {
            const int c2 = (lane & 3) << 1;
            const int b  = mt * 16 + (lane >> 2);
#pragma unroll
            for (int nt = 0; nt < NTILE; nt++) {
                const int col = nt * 8 + c2;
                ps[(kw * NROW + col    ) * 33 + b    ] = D[nt][0];
                ps[(kw * NROW + col + 1) * 33 + b    ] = D[nt][1];
                ps[(kw * NROW + col    ) * 33 + b + 8] = D[nt][2];
                ps[(kw * NROW + col + 1) * 33 + b + 8] = D[nt][3];
            }
        }
        __syncthreads();

        // ---- gates: both layers in tids 0..199
        if (tid < 200) {
            // layer-0: t = s
            if (s < SEQT) {
                float gr_ = bs[gu], gz_ = bs[8 + gu], gn_ = bs[16 + gu];
#pragma unroll
                for (int k = 0; k < 4; k++) {
                    gr_ += ps[(k * NROW +      gu) * 33 + gb];
                    gz_ += ps[(k * NROW +  8 + gu) * 33 + gb];
                    gn_ += ps[(k * NROW + 16 + gu) * 33 + gb];
                }
                const float r = fast_sig(xr0 + gr_);
                const float z = fast_sig(xz0 + gz_);
                const float n = fast_tanh(xn0 + r * gn_);
                const float hn = (1.f - z) * n + z * h0old;
                h0old = hn;
                g_h0[s & 1][gb * HID + u] = __float2half_rn(hn);
                if (s == SEQT - 1) g_h0f[gb * HID + u] = hn;
            }
            // layer-1: t = s-2 ; stash gx1 for next step
            float nR = 0.f, nZ = 0.f, nN = 0.f;
            float hr = bs[48 + gu], hz = bs[56 + gu], hn_ = bs[64 + gu];
#pragma unroll
            for (int k = 0; k < 4; k++) {
                nR  += ps[(k * NROW + 24 + gu) * 33 + gb];
                nZ  += ps[(k * NROW + 32 + gu) * 33 + gb];
                nN  += ps[(k * NROW + 40 + gu) * 33 + gb];
                hr  += ps[(k * NROW + 48 + gu) * 33 + gb];
                hz  += ps[(k * NROW + 56 + gu) * 33 + gb];
                hn_ += ps[(k * NROW + 64 + gu) * 33 + gb];
            }
            if (s >= 2) {
                const float xr = bs[24 + gu] + stR;
                const float xz = bs[32 + gu] + stZ;
                const float xn = bs[40 + gu] + stN;
                const float r = fast_sig(xr + hr);
                const float z = fast_sig(xz + hz);
                const float n = fast_tanh(xn + r * hn_);
                const float hnew = (1.f - z) * n + z * h1old;
                h1old = hnew;
                g_h1[s & 1][gb * HID + u] = __float2half_rn(hnew);
                if (s == SEQT + 1) g_h1f[gb * HID + u] = hnew;
            }
            stR = nR; stZ = nZ; stN = nN;
        }
        __syncthreads();   // h stores + ps reads done before arrive

        // ---- grid barrier (64 arrivals; monotonic; self-resets at end)
        if (s < SEQT + 1) {
            if (tid == 0) {
                red_release_add(&g_ctr, 1u);
                const unsigned target = (unsigned)(s + 1) * (unsigned)NBLK;
                while (ld_acquire(&g_ctr) < target) { }
            }
            __syncthreads();
        }
    }

    // ---- self-reset: last block to finish zeroes the counters -------------
    if (tid == 0) {
        const unsigned old = atomicAdd(&g_done, 1u);
        if (old == (unsigned)(NBLK - 1)) {
            atomicExch(&g_ctr, 0u);
            atomicExch(&g_done, 0u);
        }
    }
}

// ---------------- finalize: sig = sigmoid(h1_final . fc_w + fc_b); pack out --
__global__ void finalize_kernel(const float* __restrict__ fc_w,
                                const float* __restrict__ fc_b,
                                float* __restrict__ out)
{
    if (blockIdx.x < 100) {
        const int idx = blockIdx.x * 256 + threadIdx.x;     // 0..25599
        const float v = (idx < BATCH * HID) ? g_h0f[idx]
                                            : g_h1f[idx - BATCH * HID];
        out[25 + idx] = v;
    } else {
        const int b = threadIdx.x;
        if (b < BATCH) {
            float s = fc_b[0];
            for (int k = 0; k < HID; k++)
                s += g_h1f[b * HID + k] * fc_w[k];
            out[b] = 1.f / (1.f + expf(-s));
        }
    }
}

// ---------------- launch ----------------------------------------------------
extern "C" void kernel_launch(void* const* d_in, const int* in_sizes, int n_in,
                              void* d_out, int out_size)
{
    const int*   words  = (const int*)  d_in[0];
    const float* hidden = (const float*)d_in[1];
    const float* emb    = (const float*)d_in[2];
    const float* w_ih0  = (const float*)d_in[3];
    const float* w_hh0  = (const float*)d_in[4];
    const float* b_ih0  = (const float*)d_in[5];
    const float* b_hh0  = (const float*)d_in[6];
    const float* w_ih1  = (const float*)d_in[7];
    const float* w_hh1  = (const float*)d_in[8];
    const float* b_ih1  = (const float*)d_in[9];
    const float* b_hh1  = (const float*)d_in[10];
    const float* fc_w   = (const float*)d_in[11];
    const float* fc_b   = (const float*)d_in[12];
    float* out = (float*)d_out;

    const size_t smem_bytes =
        (size_t)(2 * HROWS * WSTR + NROW * WSTR) * sizeof(__half)
        + (size_t)(4 * NROW * 33 + 96) * sizeof(float);
    cudaFuncSetAttribute(gru_fused_kernel,
                         cudaFuncAttributeMaxDynamicSharedMemorySize,
                         (int)smem_bytes);

    // 5-launch pattern; capture idx 3 = gru_fused_kernel
    cvtA_kernel<<<MROWS, KP>>>(words, emb);                          // 0
    cvtW_kernel<<<G3, KP>>>(w_ih0);                                  // 1
    gemm_tc_kernel<<<dim3(G3 / 128, (MROWS + 127) / 128), 256>>>(    // 2
        b_ih0);
    gru_fused_kernel<<<NBLK, 256, smem_bytes>>>(                     // 3
        w_hh0, b_hh0, w_ih1, b_ih1, w_hh1, b_hh1, hidden);
    finalize_kernel<<<101, 256>>>(fc_w, fc_b, out);                  // 4
}

// round 14
// speedup vs baseline: 1.3083x; 1.0893x over previous
#include <cuda_runtime.h>
#include <cuda_fp16.h>
#include <math.h>
#include <stdint.h>

#define BATCH 25
#define SEQT  600
#define EMBD  300
#define HID   512
#define G3    1536              // 3*HID
#define MROWS (BATCH*SEQT)      // 15000
#define KP    304               // padded K for input GEMM (19 x 16)

#define WSTR  520               // smem fp16 row stride (conflict-free)
#define HROWS 26                // 25 batches + 1 zero row
#define NROW  48                // rows: 0-11 hh0 |pad| 16-27 hh1 |pad| 32-43 ih1 |pad|

// ---------------- scratch (device globals; no allocation allowed) ----------
__device__ float g_xg[(size_t)MROWS * G3];   // xg0 (layer-0 input gates)
__device__ __half g_ahi[(size_t)MROWS * KP]; // emb-gathered A, fp16 hi
__device__ __half g_alo[(size_t)MROWS * KP]; // fp16 lo (residual)
__device__ __half g_whi[(size_t)G3 * KP];    // w_ih0 fp16 hi
__device__ __half g_wlo[(size_t)G3 * KP];    // w_ih0 fp16 lo
__device__ __half g_h0[2][BATCH * HID];      // fp16 h transport (|h|<1)
__device__ __half g_h1[2][BATCH * HID];
__device__ float g_h0f[BATCH * HID];
__device__ float g_h1f[BATCH * HID];
__device__ unsigned g_ctr;                   // monotonic barrier counter
__device__ unsigned g_done;                  // completion counter (self-reset)

// ---------------- ptx helpers ----------------------------------------------
__device__ __forceinline__ void red_release_add(unsigned* p, unsigned v) {
    asm volatile("red.release.gpu.global.add.u32 [%0], %1;"
                 :: "l"(p), "r"(v) : "memory");
}
__device__ __forceinline__ unsigned ld_acquire(unsigned* p) {
    unsigned v;
    asm volatile("ld.acquire.gpu.global.u32 %0, [%1];"
                 : "=r"(v) : "l"(p) : "memory");
    return v;
}
__device__ __forceinline__ uint32_t smem_u32(const void* p) {
    uint32_t a;
    asm("{ .reg .u64 t; cvta.to.shared.u64 t, %1; cvt.u32.u64 %0, t; }"
        : "=r"(a) : "l"(p));
    return a;
}
__device__ __forceinline__ void ldm_x4(uint32_t* r, uint32_t addr) {
    asm volatile("ldmatrix.sync.aligned.m8n8.x4.shared.b16 {%0,%1,%2,%3}, [%4];"
                 : "=r"(r[0]), "=r"(r[1]), "=r"(r[2]), "=r"(r[3])
                 : "r"(addr));
}
__device__ __forceinline__ void mma_fp16(float* d, const uint32_t* a,
                                         uint32_t b0, uint32_t b1) {
    asm volatile(
        "mma.sync.aligned.m16n8k16.row.col.f32.f16.f16.f32 "
        "{%0,%1,%2,%3}, {%4,%5,%6,%7}, {%8,%9}, {%0,%1,%2,%3};"
        : "+f"(d[0]), "+f"(d[1]), "+f"(d[2]), "+f"(d[3])
        : "r"(a[0]), "r"(a[1]), "r"(a[2]), "r"(a[3]), "r"(b0), "r"(b1));
}
__device__ __forceinline__ float fast_sig(float x) {
    return __fdividef(1.f, 1.f + __expf(-x));
}
__device__ __forceinline__ float fast_tanh(float x) {
    return 1.f - __fdividef(2.f, __expf(2.f * x) + 1.f);
}

// ---------------- convert kernels: fp32 -> fp16 hi/lo (padded K) ------------
__global__ void cvtA_kernel(const int* __restrict__ words,
                            const float* __restrict__ emb)
{
    const int row = blockIdx.x;
    const int k   = threadIdx.x;
    const int w   = words[row];
    const float v = (k < EMBD) ? emb[(size_t)w * EMBD + k] : 0.f;
    const __half h = __float2half_rn(v);
    g_ahi[(size_t)row * KP + k] = h;
    g_alo[(size_t)row * KP + k] = __float2half_rn(v - __half2float(h));
}

__global__ void cvtW_kernel(const float* __restrict__ w_ih0)
{
    const int row = blockIdx.x;
    const int k   = threadIdx.x;
    const float v = (k < EMBD) ? w_ih0[(size_t)row * EMBD + k] : 0.f;
    const __half h = __float2half_rn(v);
    g_whi[(size_t)row * KP + k] = h;
    g_wlo[(size_t)row * KP + k] = __float2half_rn(v - __half2float(h));
}

// ---------------- tensor-core input GEMM (fp16 hi/lo, 3 terms) --------------
#define ASTR 24
__global__ __launch_bounds__(256) void gemm_tc_kernel(
    const float* __restrict__ bias)
{
    __shared__ __half sah[128 * ASTR], sal[128 * ASTR];
    __shared__ __half swh[128 * ASTR], swl[128 * ASTR];

    const int tid  = threadIdx.x;
    const int wid  = tid >> 5;
    const int lane = tid & 31;
    const int m0   = blockIdx.y * 128;
    const int n0   = blockIdx.x * 128;
    const int mw   = wid & 3;
    const int nw   = wid >> 2;

    uint32_t abh[2], abl[2];
    {
        const int t = lane >> 3, ir = lane & 7;
        const int ac = (t >> 1) * 8;
#pragma unroll
        for (int mt = 0; mt < 2; mt++) {
            const int ar = mw * 32 + mt * 16 + (t & 1) * 8 + ir;
            const uint32_t off = (uint32_t)(ar * ASTR + ac) * 2u;
            abh[mt] = smem_u32(sah) + off;
            abl[mt] = smem_u32(sal) + off;
        }
    }
    const int bbase = (nw * 64 + (lane >> 2)) * ASTR + (lane & 3) * 2;

    float D[2][8][4];
#pragma unroll
    for (int mt = 0; mt < 2; mt++)
#pragma unroll
        for (int j = 0; j < 8; j++)
#pragma unroll
            for (int e = 0; e < 4; e++) D[mt][j][e] = 0.f;

    const int arow  = tid >> 1;
    const int ahalf = tid & 1;
    const bool aok  = (m0 + arow) < MROWS;
    const __half* agh = g_ahi + (size_t)(m0 + arow) * KP + ahalf * 8;
    const __half* agl = g_alo + (size_t)(m0 + arow) * KP + ahalf * 8;
    const __half* wgh = g_whi + (size_t)(n0 + arow) * KP + ahalf * 8;
    const __half* wgl = g_wlo + (size_t)(n0 + arow) * KP + ahalf * 8;
    __half* dah = sah + arow * ASTR + ahalf * 8;
    __half* dal = sal + arow * ASTR + ahalf * 8;
    __half* dwh = swh + arow * ASTR + ahalf * 8;
    __half* dwl = swl + arow * ASTR + ahalf * 8;

    for (int it = 0; it < KP / 16; it++) {
        const int k0 = it * 16;
        if (aok) {
            *(uint4*)dah = *(const uint4*)(agh + k0);
            *(uint4*)dal = *(const uint4*)(agl + k0);
        }
        *(uint4*)dwh = *(const uint4*)(wgh + k0);
        *(uint4*)dwl = *(const uint4*)(wgl + k0);
        __syncthreads();

        uint32_t ah[2][4], al[2][4];
        ldm_x4(ah[0], abh[0]); ldm_x4(ah[1], abh[1]);
        ldm_x4(al[0], abl[0]); ldm_x4(al[1], abl[1]);
#pragma unroll
        for (int j = 0; j < 8; j++) {
            const int bo = bbase + j * 8 * ASTR;
            const uint32_t bh0 = *(const uint32_t*)(swh + bo);
            const uint32_t bh1 = *(const uint32_t*)(swh + bo + 8);
            const uint32_t bl0 = *(const uint32_t*)(swl + bo);
            const uint32_t bl1 = *(const uint32_t*)(swl + bo + 8);
#pragma unroll
            for (int mt = 0; mt < 2; mt++) {
                mma_fp16(D[mt][j], ah[mt], bh0, bh1);
                mma_fp16(D[mt][j], ah[mt], bl0, bl1);
                mma_fp16(D[mt][j], al[mt], bh0, bh1);
            }
        }
        __syncthreads();
    }

    const int rb = m0 + mw * 32 + (lane >> 2);
    const int cb = n0 + nw * 64 + (lane & 3) * 2;
#pragma unroll
    for (int j = 0; j < 8; j++) {
        const int c = cb + j * 8;
        const float b0v = bias[c], b1v = bias[c + 1];
#pragma unroll
        for (int mt = 0; mt < 2; mt++) {
            const int r0 = rb + mt * 16;
            if (r0 < MROWS) {
                g_xg[(size_t)r0 * G3 + c    ] = D[mt][j][0] + b0v;
                g_xg[(size_t)r0 * G3 + c + 1] = D[mt][j][1] + b1v;
            }
            if (r0 + 8 < MROWS) {
                g_xg[(size_t)(r0 + 8) * G3 + c    ] = D[mt][j][2] + b0v;
                g_xg[(size_t)(r0 + 8) * G3 + c + 1] = D[mt][j][3] + b1v;
            }
        }
    }
}

// ---------------- fused two-layer GRU: ih1 GEMM in the barrier shadow -------
// 128 blocks; block q owns units [4q,4q+4) of both layers. 48 weight rows
// (fp16 hi/lo) in smem: 0-11 hh0, 16-27 hh1, 32-43 ih1 (pads zero). Main MMA
// per step = n-tiles 0-3 (hh0 with h0, hh1 with h1). Shadow MMA (between
// barrier arrive and release) = n-tiles 4-5 (ih1 with h0, still staged); its
// D-frags cross the barrier in registers and are dumped next step.
__global__ __launch_bounds__(256, 1) void gru_fused_kernel(
    const float* __restrict__ w_hh0, const float* __restrict__ b_hh0,
    const float* __restrict__ w_ih1, const float* __restrict__ b_ih1,
    const float* __restrict__ w_hh1, const float* __restrict__ b_hh1,
    const float* __restrict__ hinit)  // [2][25][512]
{
    extern __shared__ __half smh[];
    __half* sh0 = smh;                         // [26][520]
    __half* sh1 = sh0 + HROWS * WSTR;          // [26][520]
    __half* whi = sh1 + HROWS * WSTR;          // [48][520]
    __half* wlo = whi + NROW * WSTR;           // [48][520]
    float* ps = (float*)(wlo + NROW * WSTR);   // [4][48][33]
    float* bs = ps + 4 * NROW * 33;            // [48]

    const int tid  = threadIdx.x;
    const int wid  = tid >> 5;
    const int lane = tid & 31;
    const int u0   = blockIdx.x * 4;
    const int mt   = wid & 1;          // m-tile (batch 0-15 / 16-31)
    const int kw   = wid >> 1;         // k-slice index
    const int kb   = kw * 128;         // k base (fp16 elems)

    const float* hinit0 = hinit;
    const float* hinit1 = hinit + BATCH * HID;

    // ---- prologue: weights (hi/lo), biases, zero pad rows ------------------
    {
        const float* mats[3] = { w_hh0, w_hh1, w_ih1 };
        for (int i = tid; i < NROW * 128; i += 256) {
            const int j  = i >> 7;                 // row 0..47
            const int kq = (i & 127) << 2;
            const int m  = j >> 4;                 // 0 hh0, 1 hh1, 2 ih1
            const int r  = j & 15;
            const int o  = j * WSTR + kq;
            if (r < 12) {
                const int grow = (r >> 2) * HID + u0 + (r & 3);
                float4 v = *(const float4*)(mats[m] + (size_t)grow * HID + kq);
                float vv[4] = { v.x, v.y, v.z, v.w };
#pragma unroll
                for (int e = 0; e < 4; e++) {
                    __half h = __float2half_rn(vv[e]);
                    whi[o + e] = h;
                    wlo[o + e] = __float2half_rn(vv[e] - __half2float(h));
                }
            } else {
#pragma unroll
                for (int e = 0; e < 4; e++) {
                    whi[o + e] = __float2half_rn(0.f);
                    wlo[o + e] = __float2half_rn(0.f);
                }
            }
        }
        for (int i = tid; i < WSTR; i += 256) {              // h row 25 = 0
            sh0[25 * WSTR + i] = __float2half_rn(0.f);
            sh1[25 * WSTR + i] = __float2half_rn(0.f);
        }
        if (tid < NROW) {
            const int m = tid >> 4, r = tid & 15;
            float v = 0.f;
            if (r < 12) {
                const float* bp = (m == 0) ? b_hh0 : (m == 1) ? b_hh1 : b_ih1;
                v = bp[(r >> 2) * HID + u0 + (r & 3)];
            }
            bs[tid] = v;
        }
    }

    // gate-thread identities + exact fp32 h_old in registers
    const int gb0 = tid >> 2, gu0 = tid & 3;
    const int tl  = tid - 128;
    const int gb1 = tl >> 2,  gu1 = tl & 3;
    float h0old = 0.f, h1old = 0.f;
    if (tid < 100)               h0old = hinit0[gb0 * HID + u0 + gu0];
    if (tid >= 128 && tid < 228) h1old = hinit1[gb1 * HID + u0 + gu1];

    // ldmatrix lane addressing (A = h, m16k16 tiles)
    uint32_t lb0, lb1;
    {
        const int t  = lane >> 3;
        const int ir = lane & 7;
        int arow = mt * 16 + (t & 1) * 8 + ir;
        if (arow > 25) arow = 25;                       // zeroed pad row
        const int acol = (t >> 1) * 8;
        const uint32_t aoff = (uint32_t)(arow * WSTR + kb + acol) * 2u;
        lb0 = smem_u32(sh0) + aoff;
        lb1 = smem_u32(sh1) + aoff;
    }
    const int wbase = (lane >> 2) * WSTR + ((lane & 3) << 1) + kb;

    const int r0 = mt ? 16 : 0;
    const int nr = mt ? 9  : 16;     // rows this warp stages

    float Dsh[2][4];                 // shadow (ih1) frags, cross-barrier
#pragma unroll
    for (int n = 0; n < 2; n++)
#pragma unroll
        for (int e = 0; e < 4; e++) Dsh[n][e] = 0.f;

    __syncthreads();

    // ---- prime xg for step 0
    float xr0 = 0.f, xz0 = 0.f, xn0 = 0.f;
    if (tid < 100) {
        const float* xrow = g_xg + (size_t)gb0 * SEQT * G3 + u0 + gu0;
        xr0 = __ldcg(xrow);
        xz0 = __ldcg(xrow + HID);
        xn0 = __ldcg(xrow + 2 * HID);
    }

    for (int s = 0; s <= SEQT + 1; s++) {
        // ---- warp-local staging of h0[s-1], h1[s-3] (fp16)
        if (s == 0) {
            for (int i = lane; i < nr * 32; i += 32) {
                const int r = r0 + (i >> 5), q = i & 31;
                float4 v = __ldcg((const float4*)(hinit0 + r * HID + kb) + q);
                const int o = r * WSTR + kb + q * 4;
                sh0[o + 0] = __float2half_rn(v.x);
                sh0[o + 1] = __float2half_rn(v.y);
                sh0[o + 2] = __float2half_rn(v.z);
                sh0[o + 3] = __float2half_rn(v.w);
            }
        } else {
            const __half* s0 = g_h0[(s - 1) & 1];
            for (int i = lane; i < nr * 16; i += 32) {
                const int r = r0 + (i >> 4), q = i & 15;
                float4 vh = __ldcg((const float4*)(s0 + r * HID + kb) + q);
                *((float4*)(sh0 + r * WSTR + kb) + q) = vh;
            }
        }
        if (s <= 2) {
            for (int i = lane; i < nr * 32; i += 32) {
                const int r = r0 + (i >> 5), q = i & 31;
                float4 v = __ldcg((const float4*)(hinit1 + r * HID + kb) + q);
                const int o = r * WSTR + kb + q * 4;
                sh1[o + 0] = __float2half_rn(v.x);
                sh1[o + 1] = __float2half_rn(v.y);
                sh1[o + 2] = __float2half_rn(v.z);
                sh1[o + 3] = __float2half_rn(v.w);
            }
        } else {
            const __half* s1 = g_h1[(s - 1) & 1];
            for (int i = lane; i < nr * 16; i += 32) {
                const int r = r0 + (i >> 4), q = i & 15;
                float4 vh = __ldcg((const float4*)(s1 + r * HID + kb) + q);
                *((float4*)(sh1 + r * WSTR + kb) + q) = vh;
            }
        }
        __syncwarp();

        // ---- main MMA: n-tiles 0-1 (hh0, A=h0), 2-3 (hh1, A=h1)
        float D[4][4];
#pragma unroll
        for (int n = 0; n < 4; n++)
#pragma unroll
            for (int e = 0; e < 4; e++) D[n][e] = 0.f;

#pragma unroll
        for (int ks = 0; ks < 8; ks++) {
            uint32_t a0[4], a1[4];
            ldm_x4(a0, lb0 + ks * 32);
            ldm_x4(a1, lb1 + ks * 32);
            const int wi = wbase + ks * 16;
#pragma unroll
            for (int nt = 0; nt < 4; nt++) {
                const int idx = wi + nt * 8 * WSTR;
                const uint32_t b0h = *(const uint32_t*)(whi + idx);
                const uint32_t b1h = *(const uint32_t*)(whi + idx + 8);
                const uint32_t b0l = *(const uint32_t*)(wlo + idx);
                const uint32_t b1l = *(const uint32_t*)(wlo + idx + 8);
                const uint32_t* A = (nt < 2) ? a0 : a1;
                mma_fp16(D[nt], A, b0h, b1h);
                mma_fp16(D[nt], A, b0l, b1l);
            }
        }

        // ---- dump main D (tiles 0-3) + previous shadow D (tiles 4-5)
        {
            const int c2 = (lane & 3) << 1;
            const int b  = mt * 16 + (lane >> 2);
#pragma unroll
            for (int nt = 0; nt < 4; nt++) {
                const int col = nt * 8 + c2;
                ps[(kw * NROW + col    ) * 33 + b    ] = D[nt][0];
                ps[(kw * NROW + col + 1) * 33 + b    ] = D[nt][1];
                ps[(kw * NROW + col    ) * 33 + b + 8] = D[nt][2];
                ps[(kw * NROW + col + 1) * 33 + b + 8] = D[nt][3];
            }
#pragma unroll
            for (int nt = 0; nt < 2; nt++) {
                const int col = (4 + nt) * 8 + c2;
                ps[(kw * NROW + col    ) * 33 + b    ] = Dsh[nt][0];
                ps[(kw * NROW + col + 1) * 33 + b    ] = Dsh[nt][1];
                ps[(kw * NROW + col    ) * 33 + b + 8] = Dsh[nt][2];
                ps[(kw * NROW + col + 1) * 33 + b + 8] = Dsh[nt][3];
            }
        }
        __syncthreads();

        // ---- layer-0 gates: t = s (threads 0..99)
        if (tid < 100 && s < SEQT) {
            const int u = u0 + gu0;
            float gr_ = bs[gu0], gz_ = bs[4 + gu0], gn_ = bs[8 + gu0];
#pragma unroll
            for (int k = 0; k < 4; k++) {
                gr_ += ps[(k * NROW +     gu0) * 33 + gb0];
                gz_ += ps[(k * NROW + 4 + gu0) * 33 + gb0];
                gn_ += ps[(k * NROW + 8 + gu0) * 33 + gb0];
            }
            const float r = fast_sig(xr0 + gr_);
            const float z = fast_sig(xz0 + gz_);
            const float n = fast_tanh(xn0 + r * gn_);
            const float hn = (1.f - z) * n + z * h0old;
            h0old = hn;
            g_h0[s & 1][gb0 * HID + u] = __float2half_rn(hn);
            if (s == SEQT - 1) g_h0f[gb0 * HID + u] = hn;
        }

        // ---- layer-1 gates: t = s-2 (threads 128..227)
        // hh1 terms from rows 16-27 (this step), gx1[s-2] from rows 32-43
        // (dumped this step from the shadow MMA of step s-1).
        if (tid >= 128 && tid < 228 && s >= 2) {
            const int u = u0 + gu1;
            float hr  = bs[16 + gu1], hz = bs[20 + gu1], hn_ = bs[24 + gu1];
            float xr  = bs[32 + gu1], xz = bs[36 + gu1], xn  = bs[40 + gu1];
#pragma unroll
            for (int k = 0; k < 4; k++) {
                hr  += ps[(k * NROW + 16 + gu1) * 33 + gb1];
                hz  += ps[(k * NROW + 20 + gu1) * 33 + gb1];
                hn_ += ps[(k * NROW + 24 + gu1) * 33 + gb1];
                xr  += ps[(k * NROW + 32 + gu1) * 33 + gb1];
                xz  += ps[(k * NROW + 36 + gu1) * 33 + gb1];
                xn  += ps[(k * NROW + 40 + gu1) * 33 + gb1];
            }
            const float r = fast_sig(xr + hr);
            const float z = fast_sig(xz + hz);
            const float n = fast_tanh(xn + r * hn_);
            const float hnew = (1.f - z) * n + z * h1old;
            h1old = hnew;
            g_h1[s & 1][gb1 * HID + u] = __float2half_rn(hnew);
            if (s == SEQT + 1) g_h1f[gb1 * HID + u] = hnew;
        }
        __syncthreads();   // h stores + ps reads done before arrive

        // ---- barrier arrive; SHADOW: ih1 MMA + xg prefetch; spin -----------
        if (s < SEQT + 1) {
            if (tid == 0) red_release_add(&g_ctr, 1u);

            // shadow ih1 MMA: tiles 4-5, A = h0[s-1] (sh0 still valid)
#pragma unroll
            for (int n = 0; n < 2; n++)
#pragma unroll
                for (int e = 0; e < 4; e++) Dsh[n][e] = 0.f;
#pragma unroll
            for (int ks = 0; ks < 8; ks++) {
                uint32_t a0[4];
                ldm_x4(a0, lb0 + ks * 32);
                const int wi = wbase + ks * 16;
#pragma unroll
                for (int nt = 0; nt < 2; nt++) {
                    const int idx = wi + (4 + nt) * 8 * WSTR;
                    const uint32_t b0h = *(const uint32_t*)(whi + idx);
                    const uint32_t b1h = *(const uint32_t*)(whi + idx + 8);
                    const uint32_t b0l = *(const uint32_t*)(wlo + idx);
                    const uint32_t b1l = *(const uint32_t*)(wlo + idx + 8);
                    mma_fp16(Dsh[nt], a0, b0h, b1h);
                    mma_fp16(Dsh[nt], a0, b0l, b1l);
                }
            }

            // shadow xg prefetch for step s+1 (step-indexed, barrier-free)
            if (tid < 100 && (s + 1) < SEQT) {
                const float* xrow =
                    g_xg + ((size_t)gb0 * SEQT + (s + 1)) * G3 + u0 + gu0;
                xr0 = __ldcg(xrow);
                xz0 = __ldcg(xrow + HID);
                xn0 = __ldcg(xrow + 2 * HID);
            }

            if (tid == 0) {
                const unsigned target = (unsigned)(s + 1) * 128u;
                while (ld_acquire(&g_ctr) < target) { }
            }
            __syncthreads();
        }
    }

    // ---- self-reset: last block to finish zeroes the counters -------------
    if (tid == 0) {
        const unsigned old = atomicAdd(&g_done, 1u);
        if (old == 127u) {
            atomicExch(&g_ctr, 0u);
            atomicExch(&g_done, 0u);
        }
    }
}

// ---------------- finalize: sig = sigmoid(h1_final . fc_w + fc_b); pack out --
__global__ void finalize_kernel(const float* __restrict__ fc_w,
                                const float* __restrict__ fc_b,
                                float* __restrict__ out)
{
    if (blockIdx.x < 100) {
        const int idx = blockIdx.x * 256 + threadIdx.x;     // 0..25599
        const float v = (idx < BATCH * HID) ? g_h0f[idx]
                                            : g_h1f[idx - BATCH * HID];
        out[25 + idx] = v;
    } else {
        const int b = threadIdx.x;
        if (b < BATCH) {
            float s = fc_b[0];
            for (int k = 0; k < HID; k++)
                s += g_h1f[b * HID + k] * fc_w[k];
            out[b] = 1.f / (1.f + expf(-s));
        }
    }
}

// ---------------- launch ----------------------------------------------------
extern "C" void kernel_launch(void* const* d_in, const int* in_sizes, int n_in,
                              void* d_out, int out_size)
{
    const int*   words  = (const int*)  d_in[0];
    const float* hidden = (const float*)d_in[1];
    const float* emb    = (const float*)d_in[2];
    const float* w_ih0  = (const float*)d_in[3];
    const float* w_hh0  = (const float*)d_in[4];
    const float* b_ih0  = (const float*)d_in[5];
    const float* b_hh0  = (const float*)d_in[6];
    const float* w_ih1  = (const float*)d_in[7];
    const float* w_hh1  = (const float*)d_in[8];
    const float* b_ih1  = (const float*)d_in[9];
    const float* b_hh1  = (const float*)d_in[10];
    const float* fc_w   = (const float*)d_in[11];
    const float* fc_b   = (const float*)d_in[12];
    float* out = (float*)d_out;

    const size_t smem_bytes =
        (size_t)(2 * HROWS * WSTR + 2 * NROW * WSTR) * sizeof(__half)
        + (size_t)(4 * NROW * 33 + 64) * sizeof(float);
    cudaFuncSetAttribute(gru_fused_kernel,
                         cudaFuncAttributeMaxDynamicSharedMemorySize,
                         (int)smem_bytes);

    // 5-launch pattern; capture idx 3 = gru_fused_kernel
    cvtA_kernel<<<MROWS, KP>>>(words, emb);                          // 0
    cvtW_kernel<<<G3, KP>>>(w_ih0);                                  // 1
    gemm_tc_kernel<<<dim3(G3 / 128, (MROWS + 127) / 128), 256>>>(    // 2
        b_ih0);
    gru_fused_kernel<<<128, 256, smem_bytes>>>(                      // 3
        w_hh0, b_hh0, w_ih1, b_ih1, w_hh1, b_hh1, hidden);
    finalize_kernel<<<101, 256>>>(fc_w, fc_b, out);                  // 4
}

// round 15
// speedup vs baseline: 1.3972x; 1.0680x over previous
#include <cuda_runtime.h>
#include <cuda_fp16.h>
#include <math.h>
#include <stdint.h>

#define BATCH 25
#define SEQT  600
#define EMBD  300
#define HID   512
#define G3    1536              // 3*HID
#define MROWS (BATCH*SEQT)      // 15000
#define KP    304               // padded K for input GEMM (19 x 16)

#define WSTR  520               // smem fp16 row stride (conflict-free)
#define HROWS 26                // 25 batches + 1 zero row
#define NROW  48                // rows: 0-11 hh0 |pad| 16-27 hh1 |pad| 32-43 ih1 |pad|
#define PSTR  40                // ps batch stride (conflict-free gate reads)

// ---------------- scratch (device globals; no allocation allowed) ----------
__device__ float g_xg[(size_t)MROWS * G3];   // xg0 (layer-0 input gates)
__device__ __half g_ahi[(size_t)MROWS * KP]; // emb-gathered A, fp16 hi
__device__ __half g_alo[(size_t)MROWS * KP]; // fp16 lo (residual)
__device__ __half g_whi[(size_t)G3 * KP];    // w_ih0 fp16 hi
__device__ __half g_wlo[(size_t)G3 * KP];    // w_ih0 fp16 lo
__device__ __half g_h0[2][BATCH * HID];      // fp16 h transport (|h|<1)
__device__ __half g_h1[2][BATCH * HID];
__device__ float g_h0f[BATCH * HID];
__device__ float g_h1f[BATCH * HID];
__device__ unsigned g_ctr;                   // monotonic barrier counter
__device__ unsigned g_done;                  // completion counter (self-reset)

// ---------------- ptx helpers ----------------------------------------------
__device__ __forceinline__ void red_release_add(unsigned* p, unsigned v) {
    asm volatile("red.release.gpu.global.add.u32 [%0], %1;"
                 :: "l"(p), "r"(v) : "memory");
}
__device__ __forceinline__ unsigned ld_acquire(unsigned* p) {
    unsigned v;
    asm volatile("ld.acquire.gpu.global.u32 %0, [%1];"
                 : "=r"(v) : "l"(p) : "memory");
    return v;
}
__device__ __forceinline__ uint32_t smem_u32(const void* p) {
    uint32_t a;
    asm("{ .reg .u64 t; cvta.to.shared.u64 t, %1; cvt.u32.u64 %0, t; }"
        : "=r"(a) : "l"(p));
    return a;
}
__device__ __forceinline__ void sts_release(uint32_t addr, unsigned v) {
    asm volatile("st.release.cta.shared.u32 [%0], %1;"
                 :: "r"(addr), "r"(v) : "memory");
}
__device__ __forceinline__ unsigned lds_acquire(uint32_t addr) {
    unsigned v;
    asm volatile("ld.acquire.cta.shared.u32 %0, [%1];"
                 : "=r"(v) : "r"(addr) : "memory");
    return v;
}
__device__ __forceinline__ void ldm_x4(uint32_t* r, uint32_t addr) {
    asm volatile("ldmatrix.sync.aligned.m8n8.x4.shared.b16 {%0,%1,%2,%3}, [%4];"
                 : "=r"(r[0]), "=r"(r[1]), "=r"(r[2]), "=r"(r[3])
                 : "r"(addr));
}
__device__ __forceinline__ void mma_fp16(float* d, const uint32_t* a,
                                         uint32_t b0, uint32_t b1) {
    asm volatile(
        "mma.sync.aligned.m16n8k16.row.col.f32.f16.f16.f32 "
        "{%0,%1,%2,%3}, {%4,%5,%6,%7}, {%8,%9}, {%0,%1,%2,%3};"
        : "+f"(d[0]), "+f"(d[1]), "+f"(d[2]), "+f"(d[3])
        : "r"(a[0]), "r"(a[1]), "r"(a[2]), "r"(a[3]), "r"(b0), "r"(b1));
}
__device__ __forceinline__ float fast_sig(float x) {
    return __fdividef(1.f, 1.f + __expf(-x));
}
__device__ __forceinline__ float fast_tanh(float x) {
    return 1.f - __fdividef(2.f, __expf(2.f * x) + 1.f);
}

// ---------------- convert kernels: fp32 -> fp16 hi/lo (padded K) ------------
__global__ void cvtA_kernel(const int* __restrict__ words,
                            const float* __restrict__ emb)
{
    const int row = blockIdx.x;
    const int k   = threadIdx.x;
    const int w   = words[row];
    const float v = (k < EMBD) ? emb[(size_t)w * EMBD + k] : 0.f;
    const __half h = __float2half_rn(v);
    g_ahi[(size_t)row * KP + k] = h;
    g_alo[(size_t)row * KP + k] = __float2half_rn(v - __half2float(h));
}

__global__ void cvtW_kernel(const float* __restrict__ w_ih0)
{
    const int row = blockIdx.x;
    const int k   = threadIdx.x;
    const float v = (k < EMBD) ? w_ih0[(size_t)row * EMBD + k] : 0.f;
    const __half h = __float2half_rn(v);
    g_whi[(size_t)row * KP + k] = h;
    g_wlo[(size_t)row * KP + k] = __float2half_rn(v - __half2float(h));
}

// ---------------- tensor-core input GEMM (fp16 hi/lo, 3 terms) --------------
#define ASTR 24
__global__ __launch_bounds__(256) void gemm_tc_kernel(
    const float* __restrict__ bias)
{
    __shared__ __half sah[128 * ASTR], sal[128 * ASTR];
    __shared__ __half swh[128 * ASTR], swl[128 * ASTR];

    const int tid  = threadIdx.x;
    const int wid  = tid >> 5;
    const int lane = tid & 31;
    const int m0   = blockIdx.y * 128;
    const int n0   = blockIdx.x * 128;
    const int mw   = wid & 3;
    const int nw   = wid >> 2;

    uint32_t abh[2], abl[2];
    {
        const int t = lane >> 3, ir = lane & 7;
        const int ac = (t >> 1) * 8;
#pragma unroll
        for (int mt = 0; mt < 2; mt++) {
            const int ar = mw * 32 + mt * 16 + (t & 1) * 8 + ir;
            const uint32_t off = (uint32_t)(ar * ASTR + ac) * 2u;
            abh[mt] = smem_u32(sah) + off;
            abl[mt] = smem_u32(sal) + off;
        }
    }
    const int bbase = (nw * 64 + (lane >> 2)) * ASTR + (lane & 3) * 2;

    float D[2][8][4];
#pragma unroll
    for (int mt = 0; mt < 2; mt++)
#pragma unroll
        for (int j = 0; j < 8; j++)
#pragma unroll
            for (int e = 0; e < 4; e++) D[mt][j][e] = 0.f;

    const int arow  = tid >> 1;
    const int ahalf = tid & 1;
    const bool aok  = (m0 + arow) < MROWS;
    const __half* agh = g_ahi + (size_t)(m0 + arow) * KP + ahalf * 8;
    const __half* agl = g_alo + (size_t)(m0 + arow) * KP + ahalf * 8;
    const __half* wgh = g_whi + (size_t)(n0 + arow) * KP + ahalf * 8;
    const __half* wgl = g_wlo + (size_t)(n0 + arow) * KP + ahalf * 8;
    __half* dah = sah + arow * ASTR + ahalf * 8;
    __half* dal = sal + arow * ASTR + ahalf * 8;
    __half* dwh = swh + arow * ASTR + ahalf * 8;
    __half* dwl = swl + arow * ASTR + ahalf * 8;

    for (int it = 0; it < KP / 16; it++) {
        const int k0 = it * 16;
        if (aok) {
            *(uint4*)dah = *(const uint4*)(agh + k0);
            *(uint4*)dal = *(const uint4*)(agl + k0);
        }
        *(uint4*)dwh = *(const uint4*)(wgh + k0);
        *(uint4*)dwl = *(const uint4*)(wgl + k0);
        __syncthreads();

        uint32_t ah[2][4], al[2][4];
        ldm_x4(ah[0], abh[0]); ldm_x4(ah[1], abh[1]);
        ldm_x4(al[0], abl[0]); ldm_x4(al[1], abl[1]);
#pragma unroll
        for (int j = 0; j < 8; j++) {
            const int bo = bbase + j * 8 * ASTR;
            const uint32_t bh0 = *(const uint32_t*)(swh + bo);
            const uint32_t bh1 = *(const uint32_t*)(swh + bo + 8);
            const uint32_t bl0 = *(const uint32_t*)(swl + bo);
            const uint32_t bl1 = *(const uint32_t*)(swl + bo + 8);
#pragma unroll
            for (int mt = 0; mt < 2; mt++) {
                mma_fp16(D[mt][j], ah[mt], bh0, bh1);
                mma_fp16(D[mt][j], ah[mt], bl0, bl1);
                mma_fp16(D[mt][j], al[mt], bh0, bh1);
            }
        }
        __syncthreads();
    }

    const int rb = m0 + mw * 32 + (lane >> 2);
    const int cb = n0 + nw * 64 + (lane & 3) * 2;
#pragma unroll
    for (int j = 0; j < 8; j++) {
        const int c = cb + j * 8;
        const float b0v = bias[c], b1v = bias[c + 1];
#pragma unroll
        for (int mt = 0; mt < 2; mt++) {
            const int r0 = rb + mt * 16;
            if (r0 < MROWS) {
                g_xg[(size_t)r0 * G3 + c    ] = D[mt][j][0] + b0v;
                g_xg[(size_t)r0 * G3 + c + 1] = D[mt][j][1] + b1v;
            }
            if (r0 + 8 < MROWS) {
                g_xg[(size_t)(r0 + 8) * G3 + c    ] = D[mt][j][2] + b0v;
                g_xg[(size_t)(r0 + 8) * G3 + c + 1] = D[mt][j][3] + b1v;
            }
        }
    }
}

// ---------------- fused two-layer GRU: shadow ih1 + fast release fan-out ----
// 128 blocks; block q owns units [4q,4q+4) of both layers. 48 weight rows
// (fp16 hi/lo) in smem: 0-11 hh0, 16-27 hh1, 32-43 ih1 (pads zero).
// Main MMA = tiles 0-3 (hh0.h0, hh1.h1). Shadow MMA (arrive->release window)
// = tiles 4-5 (ih1.h0); frags cross the barrier in regs. Release: warps 0-1
// poll g_ctr, first detection fans out via an smem flag (st.release.cta);
// warps 2-7 spin on the flag (29-cyc RT); per-warp self-release.
__global__ __launch_bounds__(256, 1) void gru_fused_kernel(
    const float* __restrict__ w_hh0, const float* __restrict__ b_hh0,
    const float* __restrict__ w_ih1, const float* __restrict__ b_ih1,
    const float* __restrict__ w_hh1, const float* __restrict__ b_hh1,
    const float* __restrict__ hinit)  // [2][25][512]
{
    extern __shared__ __half smh[];
    __half* sh0 = smh;                         // [26][520]
    __half* sh1 = sh0 + HROWS * WSTR;          // [26][520]
    __half* whi = sh1 + HROWS * WSTR;          // [48][520]
    __half* wlo = whi + NROW * WSTR;           // [48][520]
    float* ps = (float*)(wlo + NROW * WSTR);   // [4][48][40]
    float* bs = ps + 4 * NROW * PSTR;          // [48]
    unsigned* sflag = (unsigned*)(bs + NROW);  // release fan-out flag

    const int tid  = threadIdx.x;
    const int wid  = tid >> 5;
    const int lane = tid & 31;
    const int u0   = blockIdx.x * 4;
    const int mt   = wid & 1;          // m-tile (batch 0-15 / 16-31)
    const int kw   = wid >> 1;         // k-slice index
    const int kb   = kw * 128;         // k base (fp16 elems)
    const uint32_t sflag_a = smem_u32(sflag);

    const float* hinit0 = hinit;
    const float* hinit1 = hinit + BATCH * HID;

    // ---- prologue: weights (hi/lo), biases, zero pad rows, flag ------------
    {
        const float* mats[3] = { w_hh0, w_hh1, w_ih1 };
        for (int i = tid; i < NROW * 128; i += 256) {
            const int j  = i >> 7;                 // row 0..47
            const int kq = (i & 127) << 2;
            const int m  = j >> 4;                 // 0 hh0, 1 hh1, 2 ih1
            const int r  = j & 15;
            const int o  = j * WSTR + kq;
            if (r < 12) {
                const int grow = (r >> 2) * HID + u0 + (r & 3);
                float4 v = *(const float4*)(mats[m] + (size_t)grow * HID + kq);
                float vv[4] = { v.x, v.y, v.z, v.w };
#pragma unroll
                for (int e = 0; e < 4; e++) {
                    __half h = __float2half_rn(vv[e]);
                    whi[o + e] = h;
                    wlo[o + e] = __float2half_rn(vv[e] - __half2float(h));
                }
            } else {
#pragma unroll
                for (int e = 0; e < 4; e++) {
                    whi[o + e] = __float2half_rn(0.f);
                    wlo[o + e] = __float2half_rn(0.f);
                }
            }
        }
        for (int i = tid; i < WSTR; i += 256) {              // h row 25 = 0
            sh0[25 * WSTR + i] = __float2half_rn(0.f);
            sh1[25 * WSTR + i] = __float2half_rn(0.f);
        }
        if (tid < NROW) {
            const int m = tid >> 4, r = tid & 15;
            float v = 0.f;
            if (r < 12) {
                const float* bp = (m == 0) ? b_hh0 : (m == 1) ? b_hh1 : b_ih1;
                v = bp[(r >> 2) * HID + u0 + (r & 3)];
            }
            bs[tid] = v;
        }
        if (tid == 0) *sflag = 0u;
    }

    // gate-thread identities + exact fp32 h_old in registers
    const int gb0 = tid >> 2, gu0 = tid & 3;
    const int tl  = tid - 128;
    const int gb1 = tl >> 2,  gu1 = tl & 3;
    float h0old = 0.f, h1old = 0.f;
    if (tid < 100)               h0old = hinit0[gb0 * HID + u0 + gu0];
    if (tid >= 128 && tid < 228) h1old = hinit1[gb1 * HID + u0 + gu1];

    // ldmatrix lane addressing (A = h, m16k16 tiles)
    uint32_t lb0, lb1;
    {
        const int t  = lane >> 3;
        const int ir = lane & 7;
        int arow = mt * 16 + (t & 1) * 8 + ir;
        if (arow > 25) arow = 25;                       // zeroed pad row
        const int acol = (t >> 1) * 8;
        const uint32_t aoff = (uint32_t)(arow * WSTR + kb + acol) * 2u;
        lb0 = smem_u32(sh0) + aoff;
        lb1 = smem_u32(sh1) + aoff;
    }
    const int wbase = (lane >> 2) * WSTR + ((lane & 3) << 1) + kb;

    const int r0 = mt ? 16 : 0;
    const int nr = mt ? 9  : 16;     // rows this warp stages

    float Dsh[2][4];                 // shadow (ih1) frags, cross-barrier
#pragma unroll
    for (int n = 0; n < 2; n++)
#pragma unroll
        for (int e = 0; e < 4; e++) Dsh[n][e] = 0.f;

    __syncthreads();

    // ---- prime xg for step 0
    float xr0 = 0.f, xz0 = 0.f, xn0 = 0.f;
    if (tid < 100) {
        const float* xrow = g_xg + (size_t)gb0 * SEQT * G3 + u0 + gu0;
        xr0 = __ldcg(xrow);
        xz0 = __ldcg(xrow + HID);
        xn0 = __ldcg(xrow + 2 * HID);
    }

    for (int s = 0; s <= SEQT + 1; s++) {
        // ---- warp-local staging of h0[s-1], h1[s-3] (fp16)
        if (s == 0) {
            for (int i = lane; i < nr * 32; i += 32) {
                const int r = r0 + (i >> 5), q = i & 31;
                float4 v = __ldcg((const float4*)(hinit0 + r * HID + kb) + q);
                const int o = r * WSTR + kb + q * 4;
                sh0[o + 0] = __float2half_rn(v.x);
                sh0[o + 1] = __float2half_rn(v.y);
                sh0[o + 2] = __float2half_rn(v.z);
                sh0[o + 3] = __float2half_rn(v.w);
            }
        } else {
            const __half* s0 = g_h0[(s - 1) & 1];
            for (int i = lane; i < nr * 16; i += 32) {
                const int r = r0 + (i >> 4), q = i & 15;
                float4 vh = __ldcg((const float4*)(s0 + r * HID + kb) + q);
                *((float4*)(sh0 + r * WSTR + kb) + q) = vh;
            }
        }
        if (s <= 2) {
            for (int i = lane; i < nr * 32; i += 32) {
                const int r = r0 + (i >> 5), q = i & 31;
                float4 v = __ldcg((const float4*)(hinit1 + r * HID + kb) + q);
                const int o = r * WSTR + kb + q * 4;
                sh1[o + 0] = __float2half_rn(v.x);
                sh1[o + 1] = __float2half_rn(v.y);
                sh1[o + 2] = __float2half_rn(v.z);
                sh1[o + 3] = __float2half_rn(v.w);
            }
        } else {
            const __half* s1 = g_h1[(s - 1) & 1];
            for (int i = lane; i < nr * 16; i += 32) {
                const int r = r0 + (i >> 4), q = i & 15;
                float4 vh = __ldcg((const float4*)(s1 + r * HID + kb) + q);
                *((float4*)(sh1 + r * WSTR + kb) + q) = vh;
            }
        }
        __syncwarp();

        // ---- main MMA: n-tiles 0-1 (hh0, A=h0), 2-3 (hh1, A=h1)
        float D[4][4];
#pragma unroll
        for (int n = 0; n < 4; n++)
#pragma unroll
            for (int e = 0; e < 4; e++) D[n][e] = 0.f;

#pragma unroll
        for (int ks = 0; ks < 8; ks++) {
            uint32_t a0[4], a1[4];
            ldm_x4(a0, lb0 + ks * 32);
            ldm_x4(a1, lb1 + ks * 32);
            const int wi = wbase + ks * 16;
#pragma unroll
            for (int nt = 0; nt < 4; nt++) {
                const int idx = wi + nt * 8 * WSTR;
                const uint32_t b0h = *(const uint32_t*)(whi + idx);
                const uint32_t b1h = *(const uint32_t*)(whi + idx + 8);
                const uint32_t b0l = *(const uint32_t*)(wlo + idx);
                const uint32_t b1l = *(const uint32_t*)(wlo + idx + 8);
                const uint32_t* A = (nt < 2) ? a0 : a1;
                mma_fp16(D[nt], A, b0h, b1h);
                mma_fp16(D[nt], A, b0l, b1l);
            }
        }

        // ---- dump main D (tiles 0-3) + previous shadow D (tiles 4-5)
        {
            const int c2 = (lane & 3) << 1;
            const int b  = mt * 16 + (lane >> 2);
#pragma unroll
            for (int nt = 0; nt < 4; nt++) {
                const int col = nt * 8 + c2;
                ps[(kw * NROW + col    ) * PSTR + b    ] = D[nt][0];
                ps[(kw * NROW + col + 1) * PSTR + b    ] = D[nt][1];
                ps[(kw * NROW + col    ) * PSTR + b + 8] = D[nt][2];
                ps[(kw * NROW + col + 1) * PSTR + b + 8] = D[nt][3];
            }
#pragma unroll
            for (int nt = 0; nt < 2; nt++) {
                const int col = (4 + nt) * 8 + c2;
                ps[(kw * NROW + col    ) * PSTR + b    ] = Dsh[nt][0];
                ps[(kw * NROW + col + 1) * PSTR + b    ] = Dsh[nt][1];
                ps[(kw * NROW + col    ) * PSTR + b + 8] = Dsh[nt][2];
                ps[(kw * NROW + col + 1) * PSTR + b + 8] = Dsh[nt][3];
            }
        }
        __syncthreads();

        // ---- layer-0 gates: t = s (threads 0..99)
        if (tid < 100 && s < SEQT) {
            const int u = u0 + gu0;
            float gr_ = bs[gu0], gz_ = bs[4 + gu0], gn_ = bs[8 + gu0];
#pragma unroll
            for (int k = 0; k < 4; k++) {
                gr_ += ps[(k * NROW +     gu0) * PSTR + gb0];
                gz_ += ps[(k * NROW + 4 + gu0) * PSTR + gb0];
                gn_ += ps[(k * NROW + 8 + gu0) * PSTR + gb0];
            }
            const float r = fast_sig(xr0 + gr_);
            const float z = fast_sig(xz0 + gz_);
            const float n = fast_tanh(xn0 + r * gn_);
            const float hn = (1.f - z) * n + z * h0old;
            h0old = hn;
            g_h0[s & 1][gb0 * HID + u] = __float2half_rn(hn);
            if (s == SEQT - 1) g_h0f[gb0 * HID + u] = hn;
        }

        // ---- layer-1 gates: t = s-2 (threads 128..227)
        if (tid >= 128 && tid < 228 && s >= 2) {
            const int u = u0 + gu1;
            float hr  = bs[16 + gu1], hz = bs[20 + gu1], hn_ = bs[24 + gu1];
            float xr  = bs[32 + gu1], xz = bs[36 + gu1], xn  = bs[40 + gu1];
#pragma unroll
            for (int k = 0; k < 4; k++) {
                hr  += ps[(k * NROW + 16 + gu1) * PSTR + gb1];
                hz  += ps[(k * NROW + 20 + gu1) * PSTR + gb1];
                hn_ += ps[(k * NROW + 24 + gu1) * PSTR + gb1];
                xr  += ps[(k * NROW + 32 + gu1) * PSTR + gb1];
                xz  += ps[(k * NROW + 36 + gu1) * PSTR + gb1];
                xn  += ps[(k * NROW + 40 + gu1) * PSTR + gb1];
            }
            const float r = fast_sig(xr + hr);
            const float z = fast_sig(xz + hz);
            const float n = fast_tanh(xn + r * hn_);
            const float hnew = (1.f - z) * n + z * h1old;
            h1old = hnew;
            g_h1[s & 1][gb1 * HID + u] = __float2half_rn(hnew);
            if (s == SEQT + 1) g_h1f[gb1 * HID + u] = hnew;
        }
        __syncthreads();   // all h stores + ps reads done before arrive

        // ---- barrier arrive; SHADOW: ih1 MMA + xg prefetch; fan-out release
        if (s < SEQT + 1) {
            if (tid == 0) red_release_add(&g_ctr, 1u);

            // shadow ih1 MMA: tiles 4-5, A = h0[s-1] (sh0 still valid)
#pragma unroll
            for (int n = 0; n < 2; n++)
#pragma unroll
                for (int e = 0; e < 4; e++) Dsh[n][e] = 0.f;
#pragma unroll
            for (int ks = 0; ks < 8; ks++) {
                uint32_t a0[4];
                ldm_x4(a0, lb0 + ks * 32);
                const int wi = wbase + ks * 16;
#pragma unroll
                for (int nt = 0; nt < 2; nt++) {
                    const int idx = wi + (4 + nt) * 8 * WSTR;
                    const uint32_t b0h = *(const uint32_t*)(whi + idx);
                    const uint32_t b1h = *(const uint32_t*)(whi + idx + 8);
                    const uint32_t b0l = *(const uint32_t*)(wlo + idx);
                    const uint32_t b1l = *(const uint32_t*)(wlo + idx + 8);
                    mma_fp16(Dsh[nt], a0, b0h, b1h);
                    mma_fp16(Dsh[nt], a0, b0l, b1l);
                }
            }

            // shadow xg prefetch for step s+1 (step-indexed, barrier-free)
            if (tid < 100 && (s + 1) < SEQT) {
                const float* xrow =
                    g_xg + ((size_t)gb0 * SEQT + (s + 1)) * G3 + u0 + gu0;
                xr0 = __ldcg(xrow);
                xz0 = __ldcg(xrow + HID);
                xn0 = __ldcg(xrow + 2 * HID);
            }

            // release wait: warps 0-1 poll global (flag-check prevents any
            // post-reset spin); warps 2-7 spin on the smem flag; per-warp exit
            const unsigned rel = (unsigned)(s + 1);
            if (lane == 0) {
                if (wid < 2) {
                    const unsigned tgt = rel * 128u;
                    while (lds_acquire(sflag_a) < rel) {
                        if (ld_acquire(&g_ctr) >= tgt) {
                            sts_release(sflag_a, rel);
                            break;
                        }
                    }
                } else {
                    while (lds_acquire(sflag_a) < rel) { }
                }
            }
            __syncwarp();
        }
    }

    // ---- self-reset: last block to finish zeroes the counters -------------
    if (tid == 0) {
        const unsigned old = atomicAdd(&g_done, 1u);
        if (old == 127u) {
            atomicExch(&g_ctr, 0u);
            atomicExch(&g_done, 0u);
        }
    }
}

// ---------------- finalize: sig = sigmoid(h1_final . fc_w + fc_b); pack out --
__global__ void finalize_kernel(const float* __restrict__ fc_w,
                                const float* __restrict__ fc_b,
                                float* __restrict__ out)
{
    if (blockIdx.x < 100) {
        const int idx = blockIdx.x * 256 + threadIdx.x;     // 0..25599
        const float v = (idx < BATCH * HID) ? g_h0f[idx]
                                            : g_h1f[idx - BATCH * HID];
        out[25 + idx] = v;
    } else {
        const int b = threadIdx.x;
        if (b < BATCH) {
            float s = fc_b[0];
            for (int k = 0; k < HID; k++)
                s += g_h1f[b * HID + k] * fc_w[k];
            out[b] = 1.f / (1.f + expf(-s));
        }
    }
}

// ---------------- launch ----------------------------------------------------
extern "C" void kernel_launch(void* const* d_in, const int* in_sizes, int n_in,
                              void* d_out, int out_size)
{
    const int*   words  = (const int*)  d_in[0];
    const float* hidden = (const float*)d_in[1];
    const float* emb    = (const float*)d_in[2];
    const float* w_ih0  = (const float*)d_in[3];
    const float* w_hh0  = (const float*)d_in[4];
    const float* b_ih0  = (const float*)d_in[5];
    const float* b_hh0  = (const float*)d_in[6];
    const float* w_ih1  = (const float*)d_in[7];
    const float* w_hh1  = (const float*)d_in[8];
    const float* b_ih1  = (const float*)d_in[9];
    const float* b_hh1  = (const float*)d_in[10];
    const float* fc_w   = (const float*)d_in[11];
    const float* fc_b   = (const float*)d_in[12];
    float* out = (float*)d_out;

    const size_t smem_bytes =
        (size_t)(2 * HROWS * WSTR + 2 * NROW * WSTR) * sizeof(__half)
        + (size_t)(4 * NROW * PSTR + NROW + 16) * sizeof(float);
    cudaFuncSetAttribute(gru_fused_kernel,
                         cudaFuncAttributeMaxDynamicSharedMemorySize,
                         (int)smem_bytes);

    // 5-launch pattern; capture idx 3 = gru_fused_kernel
    cvtA_kernel<<<MROWS, KP>>>(words, emb);                          // 0
    cvtW_kernel<<<G3, KP>>>(w_ih0);                                  // 1
    gemm_tc_kernel<<<dim3(G3 / 128, (MROWS + 127) / 128), 256>>>(    // 2
        b_ih0);
    gru_fused_kernel<<<128, 256, smem_bytes>>>(                      // 3
        w_hh0, b_hh0, w_ih1, b_ih1, w_hh1, b_hh1, hidden);
    finalize_kernel<<<101, 256>>>(fc_w, fc_b, out);                  // 4
}

// round 16
// speedup vs baseline: 1.4923x; 1.0681x over previous
#include <cuda_runtime.h>
#include <cuda_fp16.h>
#include <math.h>
#include <stdint.h>

#define BATCH 25
#define SEQT  600
#define EMBD  300
#define HID   512
#define G3    1536              // 3*HID
#define MROWS (BATCH*SEQT)      // 15000
#define KP    304               // padded K for input GEMM (19 x 16)

#define WSTR  520               // smem fp16 row stride (conflict-free)
#define HROWS 26                // 25 batches + 1 zero row
#define NROW  48                // rows: 0-11 hh0 |pad| 16-27 hh1 |pad| 32-43 ih1 |pad|
#define PSTR  40                // ps batch stride (conflict-free gate reads)

// ---------------- scratch (device globals; no allocation allowed) ----------
__device__ float g_xg[(size_t)MROWS * G3];   // xg0 (layer-0 input gates)
__device__ __half g_ahi[(size_t)MROWS * KP]; // emb-gathered A, fp16 hi
__device__ __half g_alo[(size_t)MROWS * KP]; // fp16 lo (residual)
__device__ __half g_whi[(size_t)G3 * KP];    // w_ih0 fp16 hi
__device__ __half g_wlo[(size_t)G3 * KP];    // w_ih0 fp16 lo
__device__ __half g_h0[2][BATCH * HID];      // fp16 h transport (|h|<1)
__device__ __half g_h1[2][BATCH * HID];
__device__ float g_h0f[BATCH * HID];
__device__ float g_h1f[BATCH * HID];
__device__ unsigned g_ctr;                   // monotonic barrier counter
__device__ unsigned g_done;                  // completion counter (self-reset)

// ---------------- ptx helpers ----------------------------------------------
__device__ __forceinline__ void red_release_add(unsigned* p, unsigned v) {
    asm volatile("red.release.gpu.global.add.u32 [%0], %1;"
                 :: "l"(p), "r"(v) : "memory");
}
__device__ __forceinline__ unsigned ld_acquire(unsigned* p) {
    unsigned v;
    asm volatile("ld.acquire.gpu.global.u32 %0, [%1];"
                 : "=r"(v) : "l"(p) : "memory");
    return v;
}
__device__ __forceinline__ uint32_t smem_u32(const void* p) {
    uint32_t a;
    asm("{ .reg .u64 t; cvta.to.shared.u64 t, %1; cvt.u32.u64 %0, t; }"
        : "=r"(a) : "l"(p));
    return a;
}
__device__ __forceinline__ void sts_release(uint32_t addr, unsigned v) {
    asm volatile("st.release.cta.shared.u32 [%0], %1;"
                 :: "r"(addr), "r"(v) : "memory");
}
__device__ __forceinline__ unsigned lds_acquire(uint32_t addr) {
    unsigned v;
    asm volatile("ld.acquire.cta.shared.u32 %0, [%1];"
                 : "=r"(v) : "r"(addr) : "memory");
    return v;
}
__device__ __forceinline__ void ldm_x4(uint32_t* r, uint32_t addr) {
    asm volatile("ldmatrix.sync.aligned.m8n8.x4.shared.b16 {%0,%1,%2,%3}, [%4];"
                 : "=r"(r[0]), "=r"(r[1]), "=r"(r[2]), "=r"(r[3])
                 : "r"(addr));
}
__device__ __forceinline__ void mma_fp16(float* d, const uint32_t* a,
                                         uint32_t b0, uint32_t b1) {
    asm volatile(
        "mma.sync.aligned.m16n8k16.row.col.f32.f16.f16.f32 "
        "{%0,%1,%2,%3}, {%4,%5,%6,%7}, {%8,%9}, {%0,%1,%2,%3};"
        : "+f"(d[0]), "+f"(d[1]), "+f"(d[2]), "+f"(d[3])
        : "r"(a[0]), "r"(a[1]), "r"(a[2]), "r"(a[3]), "r"(b0), "r"(b1));
}
__device__ __forceinline__ float fast_sig(float x) {
    return __fdividef(1.f, 1.f + __expf(-x));
}
__device__ __forceinline__ float fast_tanh(float x) {
    return 1.f - __fdividef(2.f, __expf(2.f * x) + 1.f);
}

// ---------------- convert kernels: fp32 -> fp16 hi/lo (padded K) ------------
__global__ void cvtA_kernel(const int* __restrict__ words,
                            const float* __restrict__ emb)
{
    const int row = blockIdx.x;
    const int k   = threadIdx.x;
    const int w   = words[row];
    const float v = (k < EMBD) ? emb[(size_t)w * EMBD + k] : 0.f;
    const __half h = __float2half_rn(v);
    g_ahi[(size_t)row * KP + k] = h;
    g_alo[(size_t)row * KP + k] = __float2half_rn(v - __half2float(h));
}

__global__ void cvtW_kernel(const float* __restrict__ w_ih0)
{
    const int row = blockIdx.x;
    const int k   = threadIdx.x;
    const float v = (k < EMBD) ? w_ih0[(size_t)row * EMBD + k] : 0.f;
    const __half h = __float2half_rn(v);
    g_whi[(size_t)row * KP + k] = h;
    g_wlo[(size_t)row * KP + k] = __float2half_rn(v - __half2float(h));
}

// ---------------- tensor-core input GEMM (fp16 hi/lo, 3 terms) --------------
#define ASTR 24
__global__ __launch_bounds__(256) void gemm_tc_kernel(
    const float* __restrict__ bias)
{
    __shared__ __half sah[128 * ASTR], sal[128 * ASTR];
    __shared__ __half swh[128 * ASTR], swl[128 * ASTR];

    const int tid  = threadIdx.x;
    const int wid  = tid >> 5;
    const int lane = tid & 31;
    const int m0   = blockIdx.y * 128;
    const int n0   = blockIdx.x * 128;
    const int mw   = wid & 3;
    const int nw   = wid >> 2;

    uint32_t abh[2], abl[2];
    {
        const int t = lane >> 3, ir = lane & 7;
        const int ac = (t >> 1) * 8;
#pragma unroll
        for (int mt = 0; mt < 2; mt++) {
            const int ar = mw * 32 + mt * 16 + (t & 1) * 8 + ir;
            const uint32_t off = (uint32_t)(ar * ASTR + ac) * 2u;
            abh[mt] = smem_u32(sah) + off;
            abl[mt] = smem_u32(sal) + off;
        }
    }
    const int bbase = (nw * 64 + (lane >> 2)) * ASTR + (lane & 3) * 2;

    float D[2][8][4];
#pragma unroll
    for (int mt = 0; mt < 2; mt++)
#pragma unroll
        for (int j = 0; j < 8; j++)
#pragma unroll
            for (int e = 0; e < 4; e++) D[mt][j][e] = 0.f;

    const int arow  = tid >> 1;
    const int ahalf = tid & 1;
    const bool aok  = (m0 + arow) < MROWS;
    const __half* agh = g_ahi + (size_t)(m0 + arow) * KP + ahalf * 8;
    const __half* agl = g_alo + (size_t)(m0 + arow) * KP + ahalf * 8;
    const __half* wgh = g_whi + (size_t)(n0 + arow) * KP + ahalf * 8;
    const __half* wgl = g_wlo + (size_t)(n0 + arow) * KP + ahalf * 8;
    __half* dah = sah + arow * ASTR + ahalf * 8;
    __half* dal = sal + arow * ASTR + ahalf * 8;
    __half* dwh = swh + arow * ASTR + ahalf * 8;
    __half* dwl = swl + arow * ASTR + ahalf * 8;

    for (int it = 0; it < KP / 16; it++) {
        const int k0 = it * 16;
        if (aok) {
            *(uint4*)dah = *(const uint4*)(agh + k0);
            *(uint4*)dal = *(const uint4*)(agl + k0);
        }
        *(uint4*)dwh = *(const uint4*)(wgh + k0);
        *(uint4*)dwl = *(const uint4*)(wgl + k0);
        __syncthreads();

        uint32_t ah[2][4], al[2][4];
        ldm_x4(ah[0], abh[0]); ldm_x4(ah[1], abh[1]);
        ldm_x4(al[0], abl[0]); ldm_x4(al[1], abl[1]);
#pragma unroll
        for (int j = 0; j < 8; j++) {
            const int bo = bbase + j * 8 * ASTR;
            const uint32_t bh0 = *(const uint32_t*)(swh + bo);
            const uint32_t bh1 = *(const uint32_t*)(swh + bo + 8);
            const uint32_t bl0 = *(const uint32_t*)(swl + bo);
            const uint32_t bl1 = *(const uint32_t*)(swl + bo + 8);
#pragma unroll
            for (int mt = 0; mt < 2; mt++) {
                mma_fp16(D[mt][j], ah[mt], bh0, bh1);
                mma_fp16(D[mt][j], ah[mt], bl0, bl1);
                mma_fp16(D[mt][j], al[mt], bh0, bh1);
            }
        }
        __syncthreads();
    }

    const int rb = m0 + mw * 32 + (lane >> 2);
    const int cb = n0 + nw * 64 + (lane & 3) * 2;
#pragma unroll
    for (int j = 0; j < 8; j++) {
        const int c = cb + j * 8;
        const float b0v = bias[c], b1v = bias[c + 1];
#pragma unroll
        for (int mt = 0; mt < 2; mt++) {
            const int r0 = rb + mt * 16;
            if (r0 < MROWS) {
                g_xg[(size_t)r0 * G3 + c    ] = D[mt][j][0] + b0v;
                g_xg[(size_t)r0 * G3 + c + 1] = D[mt][j][1] + b1v;
            }
            if (r0 + 8 < MROWS) {
                g_xg[(size_t)(r0 + 8) * G3 + c    ] = D[mt][j][2] + b0v;
                g_xg[(size_t)(r0 + 8) * G3 + c + 1] = D[mt][j][3] + b1v;
            }
        }
    }
}

// ---------------- fused two-layer GRU: hi-only main MMA + shadow ih1 --------
// 128 blocks; block q owns units [4q,4q+4) of both layers. 48 weight rows in
// smem: 0-11 hh0, 16-27 hh1, 32-43 ih1 (pads zero). Main MMA (critical path)
// = tiles 0-3, W-hi ONLY (32 HMMA; quantization ~2^-11, measured rel_err
// 2.3e-4 in round 13 — 4x inside threshold). Shadow MMA (barrier window)
// = tiles 4-5 (ih1.h0) with hi+lo (free). Release via smem-flag fan-out.
__global__ __launch_bounds__(256, 1) void gru_fused_kernel(
    const float* __restrict__ w_hh0, const float* __restrict__ b_hh0,
    const float* __restrict__ w_ih1, const float* __restrict__ b_ih1,
    const float* __restrict__ w_hh1, const float* __restrict__ b_hh1,
    const float* __restrict__ hinit)  // [2][25][512]
{
    extern __shared__ __half smh[];
    __half* sh0 = smh;                         // [26][520]
    __half* sh1 = sh0 + HROWS * WSTR;          // [26][520]
    __half* whi = sh1 + HROWS * WSTR;          // [48][520]
    __half* wlo = whi + NROW * WSTR;           // [48][520] (only rows 32-43 used)
    float* ps = (float*)(wlo + NROW * WSTR);   // [4][48][40]
    float* bs = ps + 4 * NROW * PSTR;          // [48]
    unsigned* sflag = (unsigned*)(bs + NROW);  // release fan-out flag

    const int tid  = threadIdx.x;
    const int wid  = tid >> 5;
    const int lane = tid & 31;
    const int u0   = blockIdx.x * 4;
    const int mt   = wid & 1;          // m-tile (batch 0-15 / 16-31)
    const int kw   = wid >> 1;         // k-slice index
    const int kb   = kw * 128;         // k base (fp16 elems)
    const uint32_t sflag_a = smem_u32(sflag);

    const float* hinit0 = hinit;
    const float* hinit1 = hinit + BATCH * HID;

    // ---- prologue: weights (hi; lo only for ih1 rows), biases, pads, flag --
    {
        const float* mats[3] = { w_hh0, w_hh1, w_ih1 };
        for (int i = tid; i < NROW * 128; i += 256) {
            const int j  = i >> 7;                 // row 0..47
            const int kq = (i & 127) << 2;
            const int m  = j >> 4;                 // 0 hh0, 1 hh1, 2 ih1
            const int r  = j & 15;
            const int o  = j * WSTR + kq;
            if (r < 12) {
                const int grow = (r >> 2) * HID + u0 + (r & 3);
                float4 v = *(const float4*)(mats[m] + (size_t)grow * HID + kq);
                float vv[4] = { v.x, v.y, v.z, v.w };
#pragma unroll
                for (int e = 0; e < 4; e++) {
                    __half h = __float2half_rn(vv[e]);
                    whi[o + e] = h;
                    wlo[o + e] = __float2half_rn(vv[e] - __half2float(h));
                }
            } else {
#pragma unroll
                for (int e = 0; e < 4; e++) {
                    whi[o + e] = __float2half_rn(0.f);
                    wlo[o + e] = __float2half_rn(0.f);
                }
            }
        }
        for (int i = tid; i < WSTR; i += 256) {              // h row 25 = 0
            sh0[25 * WSTR + i] = __float2half_rn(0.f);
            sh1[25 * WSTR + i] = __float2half_rn(0.f);
        }
        if (tid < NROW) {
            const int m = tid >> 4, r = tid & 15;
            float v = 0.f;
            if (r < 12) {
                const float* bp = (m == 0) ? b_hh0 : (m == 1) ? b_hh1 : b_ih1;
                v = bp[(r >> 2) * HID + u0 + (r & 3)];
            }
            bs[tid] = v;
        }
        if (tid == 0) *sflag = 0u;
    }

    // gate-thread identities + exact fp32 h_old in registers
    const int gb0 = tid >> 2, gu0 = tid & 3;
    const int tl  = tid - 128;
    const int gb1 = tl >> 2,  gu1 = tl & 3;
    float h0old = 0.f, h1old = 0.f;
    if (tid < 100)               h0old = hinit0[gb0 * HID + u0 + gu0];
    if (tid >= 128 && tid < 228) h1old = hinit1[gb1 * HID + u0 + gu1];

    // ldmatrix lane addressing (A = h, m16k16 tiles)
    uint32_t lb0, lb1;
    {
        const int t  = lane >> 3;
        const int ir = lane & 7;
        int arow = mt * 16 + (t & 1) * 8 + ir;
        if (arow > 25) arow = 25;                       // zeroed pad row
        const int acol = (t >> 1) * 8;
        const uint32_t aoff = (uint32_t)(arow * WSTR + kb + acol) * 2u;
        lb0 = smem_u32(sh0) + aoff;
        lb1 = smem_u32(sh1) + aoff;
    }
    const int wbase = (lane >> 2) * WSTR + ((lane & 3) << 1) + kb;

    const int r0 = mt ? 16 : 0;
    const int nr = mt ? 9  : 16;     // rows this warp stages

    float Dsh[2][4];                 // shadow (ih1) frags, cross-barrier
#pragma unroll
    for (int n = 0; n < 2; n++)
#pragma unroll
        for (int e = 0; e < 4; e++) Dsh[n][e] = 0.f;

    __syncthreads();

    // ---- prime xg for step 0
    float xr0 = 0.f, xz0 = 0.f, xn0 = 0.f;
    if (tid < 100) {
        const float* xrow = g_xg + (size_t)gb0 * SEQT * G3 + u0 + gu0;
        xr0 = __ldcg(xrow);
        xz0 = __ldcg(xrow + HID);
        xn0 = __ldcg(xrow + 2 * HID);
    }

    for (int s = 0; s <= SEQT + 1; s++) {
        // ---- warp-local staging of h0[s-1], h1[s-3] (fp16)
        if (s == 0) {
            for (int i = lane; i < nr * 32; i += 32) {
                const int r = r0 + (i >> 5), q = i & 31;
                float4 v = __ldcg((const float4*)(hinit0 + r * HID + kb) + q);
                const int o = r * WSTR + kb + q * 4;
                sh0[o + 0] = __float2half_rn(v.x);
                sh0[o + 1] = __float2half_rn(v.y);
                sh0[o + 2] = __float2half_rn(v.z);
                sh0[o + 3] = __float2half_rn(v.w);
            }
        } else {
            const __half* s0 = g_h0[(s - 1) & 1];
            for (int i = lane; i < nr * 16; i += 32) {
                const int r = r0 + (i >> 4), q = i & 15;
                float4 vh = __ldcg((const float4*)(s0 + r * HID + kb) + q);
                *((float4*)(sh0 + r * WSTR + kb) + q) = vh;
            }
        }
        if (s <= 2) {
            for (int i = lane; i < nr * 32; i += 32) {
                const int r = r0 + (i >> 5), q = i & 31;
                float4 v = __ldcg((const float4*)(hinit1 + r * HID + kb) + q);
                const int o = r * WSTR + kb + q * 4;
                sh1[o + 0] = __float2half_rn(v.x);
                sh1[o + 1] = __float2half_rn(v.y);
                sh1[o + 2] = __float2half_rn(v.z);
                sh1[o + 3] = __float2half_rn(v.w);
            }
        } else {
            const __half* s1 = g_h1[(s - 1) & 1];
            for (int i = lane; i < nr * 16; i += 32) {
                const int r = r0 + (i >> 4), q = i & 15;
                float4 vh = __ldcg((const float4*)(s1 + r * HID + kb) + q);
                *((float4*)(sh1 + r * WSTR + kb) + q) = vh;
            }
        }
        __syncwarp();

        // ---- main MMA (critical path): tiles 0-1 (hh0.h0), 2-3 (hh1.h1),
        //      W-hi only -> 32 HMMA
        float D[4][4];
#pragma unroll
        for (int n = 0; n < 4; n++)
#pragma unroll
            for (int e = 0; e < 4; e++) D[n][e] = 0.f;

#pragma unroll
        for (int ks = 0; ks < 8; ks++) {
            uint32_t a0[4], a1[4];
            ldm_x4(a0, lb0 + ks * 32);
            ldm_x4(a1, lb1 + ks * 32);
            const int wi = wbase + ks * 16;
#pragma unroll
            for (int nt = 0; nt < 4; nt++) {
                const int idx = wi + nt * 8 * WSTR;
                const uint32_t b0h = *(const uint32_t*)(whi + idx);
                const uint32_t b1h = *(const uint32_t*)(whi + idx + 8);
                const uint32_t* A = (nt < 2) ? a0 : a1;
                mma_fp16(D[nt], A, b0h, b1h);
            }
        }

        // ---- dump main D (tiles 0-3) + previous shadow D (tiles 4-5)
        {
            const int c2 = (lane & 3) << 1;
            const int b  = mt * 16 + (lane >> 2);
#pragma unroll
            for (int nt = 0; nt < 4; nt++) {
                const int col = nt * 8 + c2;
                ps[(kw * NROW + col    ) * PSTR + b    ] = D[nt][0];
                ps[(kw * NROW + col + 1) * PSTR + b    ] = D[nt][1];
                ps[(kw * NROW + col    ) * PSTR + b + 8] = D[nt][2];
                ps[(kw * NROW + col + 1) * PSTR + b + 8] = D[nt][3];
            }
#pragma unroll
            for (int nt = 0; nt < 2; nt++) {
                const int col = (4 + nt) * 8 + c2;
                ps[(kw * NROW + col    ) * PSTR + b    ] = Dsh[nt][0];
                ps[(kw * NROW + col + 1) * PSTR + b    ] = Dsh[nt][1];
                ps[(kw * NROW + col    ) * PSTR + b + 8] = Dsh[nt][2];
                ps[(kw * NROW + col + 1) * PSTR + b + 8] = Dsh[nt][3];
            }
        }
        __syncthreads();

        // ---- layer-0 gates: t = s (threads 0..99)
        if (tid < 100 && s < SEQT) {
            const int u = u0 + gu0;
            float gr_ = bs[gu0], gz_ = bs[4 + gu0], gn_ = bs[8 + gu0];
#pragma unroll
            for (int k = 0; k < 4; k++) {
                gr_ += ps[(k * NROW +     gu0) * PSTR + gb0];
                gz_ += ps[(k * NROW + 4 + gu0) * PSTR + gb0];
                gn_ += ps[(k * NROW + 8 + gu0) * PSTR + gb0];
            }
            const float r = fast_sig(xr0 + gr_);
            const float z = fast_sig(xz0 + gz_);
            const float n = fast_tanh(xn0 + r * gn_);
            const float hn = (1.f - z) * n + z * h0old;
            h0old = hn;
            g_h0[s & 1][gb0 * HID + u] = __float2half_rn(hn);
            if (s == SEQT - 1) g_h0f[gb0 * HID + u] = hn;
        }

        // ---- layer-1 gates: t = s-2 (threads 128..227)
        if (tid >= 128 && tid < 228 && s >= 2) {
            const int u = u0 + gu1;
            float hr  = bs[16 + gu1], hz = bs[20 + gu1], hn_ = bs[24 + gu1];
            float xr  = bs[32 + gu1], xz = bs[36 + gu1], xn  = bs[40 + gu1];
#pragma unroll
            for (int k = 0; k < 4; k++) {
                hr  += ps[(k * NROW + 16 + gu1) * PSTR + gb1];
                hz  += ps[(k * NROW + 20 + gu1) * PSTR + gb1];
                hn_ += ps[(k * NROW + 24 + gu1) * PSTR + gb1];
                xr  += ps[(k * NROW + 32 + gu1) * PSTR + gb1];
                xz  += ps[(k * NROW + 36 + gu1) * PSTR + gb1];
                xn  += ps[(k * NROW + 40 + gu1) * PSTR + gb1];
            }
            const float r = fast_sig(xr + hr);
            const float z = fast_sig(xz + hz);
            const float n = fast_tanh(xn + r * hn_);
            const float hnew = (1.f - z) * n + z * h1old;
            h1old = hnew;
            g_h1[s & 1][gb1 * HID + u] = __float2half_rn(hnew);
            if (s == SEQT + 1) g_h1f[gb1 * HID + u] = hnew;
        }
        __syncthreads();   // all h stores + ps reads done before arrive

        // ---- barrier arrive; SHADOW: ih1 MMA (hi+lo) + xg prefetch; release
        if (s < SEQT + 1) {
            if (tid == 0) red_release_add(&g_ctr, 1u);

            // shadow ih1 MMA: tiles 4-5, A = h0[s-1] (sh0 still valid)
#pragma unroll
            for (int n = 0; n < 2; n++)
#pragma unroll
                for (int e = 0; e < 4; e++) Dsh[n][e] = 0.f;
#pragma unroll
            for (int ks = 0; ks < 8; ks++) {
                uint32_t a0[4];
                ldm_x4(a0, lb0 + ks * 32);
                const int wi = wbase + ks * 16;
#pragma unroll
                for (int nt = 0; nt < 2; nt++) {
                    const int idx = wi + (4 + nt) * 8 * WSTR;
                    const uint32_t b0h = *(const uint32_t*)(whi + idx);
                    const uint32_t b1h = *(const uint32_t*)(whi + idx + 8);
                    const uint32_t b0l = *(const uint32_t*)(wlo + idx);
                    const uint32_t b1l = *(const uint32_t*)(wlo + idx + 8);
                    mma_fp16(Dsh[nt], a0, b0h, b1h);
                    mma_fp16(Dsh[nt], a0, b0l, b1l);
                }
            }

            // shadow xg prefetch for step s+1 (step-indexed, barrier-free)
            if (tid < 100 && (s + 1) < SEQT) {
                const float* xrow =
                    g_xg + ((size_t)gb0 * SEQT + (s + 1)) * G3 + u0 + gu0;
                xr0 = __ldcg(xrow);
                xz0 = __ldcg(xrow + HID);
                xn0 = __ldcg(xrow + 2 * HID);
            }

            // release wait: warps 0-1 poll global (flag-check prevents any
            // post-reset spin); warps 2-7 spin on the smem flag; per-warp exit
            const unsigned rel = (unsigned)(s + 1);
            if (lane == 0) {
                if (wid < 2) {
                    const unsigned tgt = rel * 128u;
                    while (lds_acquire(sflag_a) < rel) {
                        if (ld_acquire(&g_ctr) >= tgt) {
                            sts_release(sflag_a, rel);
                            break;
                        }
                    }
                } else {
                    while (lds_acquire(sflag_a) < rel) { }
                }
            }
            __syncwarp();
        }
    }

    // ---- self-reset: last block to finish zeroes the counters -------------
    if (tid == 0) {
        const unsigned old = atomicAdd(&g_done, 1u);
        if (old == 127u) {
            atomicExch(&g_ctr, 0u);
            atomicExch(&g_done, 0u);
        }
    }
}

// ---------------- finalize: sig = sigmoid(h1_final . fc_w + fc_b); pack out --
__global__ void finalize_kernel(const float* __restrict__ fc_w,
                                const float* __restrict__ fc_b,
                                float* __restrict__ out)
{
    if (blockIdx.x < 100) {
        const int idx = blockIdx.x * 256 + threadIdx.x;     // 0..25599
        const float v = (idx < BATCH * HID) ? g_h0f[idx]
                                            : g_h1f[idx - BATCH * HID];
        out[25 + idx] = v;
    } else {
        const int b = threadIdx.x;
        if (b < BATCH) {
            float s = fc_b[0];
            for (int k = 0; k < HID; k++)
                s += g_h1f[b * HID + k] * fc_w[k];
            out[b] = 1.f / (1.f + expf(-s));
        }
    }
}

// ---------------- launch ----------------------------------------------------
extern "C" void kernel_launch(void* const* d_in, const int* in_sizes, int n_in,
                              void* d_out, int out_size)
{
    const int*   words  = (const int*)  d_in[0];
    const float* hidden = (const float*)d_in[1];
    const float* emb    = (const float*)d_in[2];
    const float* w_ih0  = (const float*)d_in[3];
    const float* w_hh0  = (const float*)d_in[4];
    const float* b_ih0  = (const float*)d_in[5];
    const float* b_hh0  = (const float*)d_in[6];
    const float* w_ih1  = (const float*)d_in[7];
    const float* w_hh1  = (const float*)d_in[8];
    const float* b_ih1  = (const float*)d_in[9];
    const float* b_hh1  = (const float*)d_in[10];
    const float* fc_w   = (const float*)d_in[11];
    const float* fc_b   = (const float*)d_in[12];
    float* out = (float*)d_out;

    const size_t smem_bytes =
        (size_t)(2 * HROWS * WSTR + 2 * NROW * WSTR) * sizeof(__half)
        + (size_t)(4 * NROW * PSTR + NROW + 16) * sizeof(float);
    cudaFuncSetAttribute(gru_fused_kernel,
                         cudaFuncAttributeMaxDynamicSharedMemorySize,
                         (int)smem_bytes);

    // 5-launch pattern; capture idx 3 = gru_fused_kernel
    cvtA_kernel<<<MROWS, KP>>>(words, emb);                          // 0
    cvtW_kernel<<<G3, KP>>>(w_ih0);                                  // 1
    gemm_tc_kernel<<<dim3(G3 / 128, (MROWS + 127) / 128), 256>>>(    // 2
        b_ih0);
    gru_fused_kernel<<<128, 256, smem_bytes>>>(                      // 3
        w_hh0, b_hh0, w_ih1, b_ih1, w_hh1, b_hh1, hidden);
    finalize_kernel<<<101, 256>>>(fc_w, fc_b, out);                  // 4
}

// round 17
// speedup vs baseline: 1.5833x; 1.0609x over previous
#include <cuda_runtime.h>
#include <cuda_fp16.h>
#include <math.h>
#include <stdint.h>

#define BATCH 25
#define SEQT  600
#define EMBD  300
#define HID   512
#define G3    1536              // 3*HID
#define MROWS (BATCH*SEQT)      // 15000
#define KP    304               // padded K for input GEMM (19 x 16)

#define WSTR  520               // smem fp16 row stride (conflict-free)
#define HROWS 26                // 25 batches + 1 zero row
#define NROW  48                // rows: 0-11 hh0 |pad| 16-27 hh1 |pad| 32-43 ih1 |pad|
#define PSTR  40                // ps batch stride (conflict-free gate reads)

// ---------------- scratch (device globals; no allocation allowed) ----------
__device__ float g_xg[(size_t)MROWS * G3];   // xg0 (layer-0 input gates)
__device__ __half g_ahi[(size_t)MROWS * KP]; // emb-gathered A, fp16 hi
__device__ __half g_whi[(size_t)G3 * KP];    // w_ih0 fp16 hi
__device__ __half g_wlo[(size_t)G3 * KP];    // w_ih0 fp16 lo
__device__ __half g_h0[2][BATCH * HID];      // fp16 h transport (|h|<1)
__device__ __half g_h1[2][BATCH * HID];
__device__ float g_h0f[BATCH * HID];
__device__ float g_h1f[BATCH * HID];
__device__ unsigned g_ctr;                   // monotonic barrier counter
__device__ unsigned g_done;                  // completion counter (self-reset)

// ---------------- ptx helpers ----------------------------------------------
__device__ __forceinline__ void red_release_add(unsigned* p, unsigned v) {
    asm volatile("red.release.gpu.global.add.u32 [%0], %1;"
                 :: "l"(p), "r"(v) : "memory");
}
__device__ __forceinline__ unsigned ld_acquire(unsigned* p) {
    unsigned v;
    asm volatile("ld.acquire.gpu.global.u32 %0, [%1];"
                 : "=r"(v) : "l"(p) : "memory");
    return v;
}
__device__ __forceinline__ uint32_t smem_u32(const void* p) {
    uint32_t a;
    asm("{ .reg .u64 t; cvta.to.shared.u64 t, %1; cvt.u32.u64 %0, t; }"
        : "=r"(a) : "l"(p));
    return a;
}
__device__ __forceinline__ void sts_release(uint32_t addr, unsigned v) {
    asm volatile("st.release.cta.shared.u32 [%0], %1;"
                 :: "r"(addr), "r"(v) : "memory");
}
__device__ __forceinline__ unsigned lds_acquire(uint32_t addr) {
    unsigned v;
    asm volatile("ld.acquire.cta.shared.u32 %0, [%1];"
                 : "=r"(v) : "r"(addr) : "memory");
    return v;
}
__device__ __forceinline__ void ldm_x4(uint32_t* r, uint32_t addr) {
    asm volatile("ldmatrix.sync.aligned.m8n8.x4.shared.b16 {%0,%1,%2,%3}, [%4];"
                 : "=r"(r[0]), "=r"(r[1]), "=r"(r[2]), "=r"(r[3])
                 : "r"(addr));
}
__device__ __forceinline__ void mma_fp16(float* d, const uint32_t* a,
                                         uint32_t b0, uint32_t b1) {
    asm volatile(
        "mma.sync.aligned.m16n8k16.row.col.f32.f16.f16.f32 "
        "{%0,%1,%2,%3}, {%4,%5,%6,%7}, {%8,%9}, {%0,%1,%2,%3};"
        : "+f"(d[0]), "+f"(d[1]), "+f"(d[2]), "+f"(d[3])
        : "r"(a[0]), "r"(a[1]), "r"(a[2]), "r"(a[3]), "r"(b0), "r"(b1));
}
__device__ __forceinline__ float fast_sig(float x) {
    return __fdividef(1.f, 1.f + __expf(-x));
}
__device__ __forceinline__ float fast_tanh(float x) {
    return 1.f - __fdividef(2.f, __expf(2.f * x) + 1.f);
}

// ---------------- convert kernels: fp32 -> fp16 (padded K) ------------------
__global__ void cvtA_kernel(const int* __restrict__ words,
                            const float* __restrict__ emb)
{
    const int row = blockIdx.x;
    const int k   = threadIdx.x;
    const int w   = words[row];
    const float v = (k < EMBD) ? emb[(size_t)w * EMBD + k] : 0.f;
    g_ahi[(size_t)row * KP + k] = __float2half_rn(v);
}

__global__ void cvtW_kernel(const float* __restrict__ w_ih0)
{
    const int row = blockIdx.x;
    const int k   = threadIdx.x;
    const float v = (k < EMBD) ? w_ih0[(size_t)row * EMBD + k] : 0.f;
    const __half h = __float2half_rn(v);
    g_whi[(size_t)row * KP + k] = h;
    g_wlo[(size_t)row * KP + k] = __float2half_rn(v - __half2float(h));
}

// ---------------- tensor-core input GEMM (2 terms: Ahi.Whi + Ahi.Wlo) -------
#define ASTR 24
__global__ __launch_bounds__(256) void gemm_tc_kernel(
    const float* __restrict__ bias)
{
    __shared__ __half sah[128 * ASTR];
    __shared__ __half swh[128 * ASTR], swl[128 * ASTR];

    const int tid  = threadIdx.x;
    const int wid  = tid >> 5;
    const int lane = tid & 31;
    const int m0   = blockIdx.y * 128;
    const int n0   = blockIdx.x * 128;
    const int mw   = wid & 3;
    const int nw   = wid >> 2;

    uint32_t abh[2];
    {
        const int t = lane >> 3, ir = lane & 7;
        const int ac = (t >> 1) * 8;
#pragma unroll
        for (int mt = 0; mt < 2; mt++) {
            const int ar = mw * 32 + mt * 16 + (t & 1) * 8 + ir;
            abh[mt] = smem_u32(sah) + (uint32_t)(ar * ASTR + ac) * 2u;
        }
    }
    const int bbase = (nw * 64 + (lane >> 2)) * ASTR + (lane & 3) * 2;

    float D[2][8][4];
#pragma unroll
    for (int mt = 0; mt < 2; mt++)
#pragma unroll
        for (int j = 0; j < 8; j++)
#pragma unroll
            for (int e = 0; e < 4; e++) D[mt][j][e] = 0.f;

    const int arow  = tid >> 1;
    const int ahalf = tid & 1;
    const bool aok  = (m0 + arow) < MROWS;
    const __half* agh = g_ahi + (size_t)(m0 + arow) * KP + ahalf * 8;
    const __half* wgh = g_whi + (size_t)(n0 + arow) * KP + ahalf * 8;
    const __half* wgl = g_wlo + (size_t)(n0 + arow) * KP + ahalf * 8;
    __half* dah = sah + arow * ASTR + ahalf * 8;
    __half* dwh = swh + arow * ASTR + ahalf * 8;
    __half* dwl = swl + arow * ASTR + ahalf * 8;

    for (int it = 0; it < KP / 16; it++) {
        const int k0 = it * 16;
        if (aok) *(uint4*)dah = *(const uint4*)(agh + k0);
        *(uint4*)dwh = *(const uint4*)(wgh + k0);
        *(uint4*)dwl = *(const uint4*)(wgl + k0);
        __syncthreads();

        uint32_t ah[2][4];
        ldm_x4(ah[0], abh[0]); ldm_x4(ah[1], abh[1]);
#pragma unroll
        for (int j = 0; j < 8; j++) {
            const int bo = bbase + j * 8 * ASTR;
            const uint32_t bh0 = *(const uint32_t*)(swh + bo);
            const uint32_t bh1 = *(const uint32_t*)(swh + bo + 8);
            const uint32_t bl0 = *(const uint32_t*)(swl + bo);
            const uint32_t bl1 = *(const uint32_t*)(swl + bo + 8);
#pragma unroll
            for (int mt = 0; mt < 2; mt++) {
                mma_fp16(D[mt][j], ah[mt], bh0, bh1);
                mma_fp16(D[mt][j], ah[mt], bl0, bl1);
            }
        }
        __syncthreads();
    }

    const int rb = m0 + mw * 32 + (lane >> 2);
    const int cb = n0 + nw * 64 + (lane & 3) * 2;
#pragma unroll
    for (int j = 0; j < 8; j++) {
        const int c = cb + j * 8;
        const float b0v = bias[c], b1v = bias[c + 1];
#pragma unroll
        for (int mt = 0; mt < 2; mt++) {
            const int r0 = rb + mt * 16;
            if (r0 < MROWS) {
                g_xg[(size_t)r0 * G3 + c    ] = D[mt][j][0] + b0v;
                g_xg[(size_t)r0 * G3 + c + 1] = D[mt][j][1] + b1v;
            }
            if (r0 + 8 < MROWS) {
                g_xg[(size_t)(r0 + 8) * G3 + c    ] = D[mt][j][2] + b0v;
                g_xg[(size_t)(r0 + 8) * G3 + c + 1] = D[mt][j][3] + b1v;
            }
        }
    }
}

// ---------------- fused two-layer GRU: reg-resident main B + shadow ih1 -----
// 128 blocks; block q owns units [4q,4q+4) of both layers. Main MMA (critical
// path) = tiles 0-3, W-hi only, B-fragments in REGISTERS (64 regs, loaded
// once). Shadow MMA (barrier window) = tiles 4-5 (ih1.h0) hi+lo from smem.
// Release via smem-flag fan-out.
__global__ __launch_bounds__(256, 1) void gru_fused_kernel(
    const float* __restrict__ w_hh0, const float* __restrict__ b_hh0,
    const float* __restrict__ w_ih1, const float* __restrict__ b_ih1,
    const float* __restrict__ w_hh1, const float* __restrict__ b_hh1,
    const float* __restrict__ hinit)  // [2][25][512]
{
    extern __shared__ __half smh[];
    __half* sh0 = smh;                         // [26][520]
    __half* sh1 = sh0 + HROWS * WSTR;          // [26][520]
    __half* whi = sh1 + HROWS * WSTR;          // [48][520]
    __half* wlo = whi + NROW * WSTR;           // [48][520] (rows 32-43 used)
    float* ps = (float*)(wlo + NROW * WSTR);   // [4][48][40]
    float* bs = ps + 4 * NROW * PSTR;          // [48]
    unsigned* sflag = (unsigned*)(bs + NROW);  // release fan-out flag

    const int tid  = threadIdx.x;
    const int wid  = tid >> 5;
    const int lane = tid & 31;
    const int u0   = blockIdx.x * 4;
    const int mt   = wid & 1;          // m-tile (batch 0-15 / 16-31)
    const int kw   = wid >> 1;         // k-slice index
    const int kb   = kw * 128;         // k base (fp16 elems)
    const uint32_t sflag_a = smem_u32(sflag);

    const float* hinit0 = hinit;
    const float* hinit1 = hinit + BATCH * HID;

    // ---- prologue: weights (hi; lo only matters for ih1), biases, pads -----
    {
        const float* mats[3] = { w_hh0, w_hh1, w_ih1 };
        for (int i = tid; i < NROW * 128; i += 256) {
            const int j  = i >> 7;                 // row 0..47
            const int kq = (i & 127) << 2;
            const int m  = j >> 4;                 // 0 hh0, 1 hh1, 2 ih1
            const int r  = j & 15;
            const int o  = j * WSTR + kq;
            if (r < 12) {
                const int grow = (r >> 2) * HID + u0 + (r & 3);
                float4 v = *(const float4*)(mats[m] + (size_t)grow * HID + kq);
                float vv[4] = { v.x, v.y, v.z, v.w };
#pragma unroll
                for (int e = 0; e < 4; e++) {
                    __half h = __float2half_rn(vv[e]);
                    whi[o + e] = h;
                    wlo[o + e] = __float2half_rn(vv[e] - __half2float(h));
                }
            } else {
#pragma unroll
                for (int e = 0; e < 4; e++) {
                    whi[o + e] = __float2half_rn(0.f);
                    wlo[o + e] = __float2half_rn(0.f);
                }
            }
        }
        for (int i = tid; i < WSTR; i += 256) {              // h row 25 = 0
            sh0[25 * WSTR + i] = __float2half_rn(0.f);
            sh1[25 * WSTR + i] = __float2half_rn(0.f);
        }
        if (tid < NROW) {
            const int m = tid >> 4, r = tid & 15;
            float v = 0.f;
            if (r < 12) {
                const float* bp = (m == 0) ? b_hh0 : (m == 1) ? b_hh1 : b_ih1;
                v = bp[(r >> 2) * HID + u0 + (r & 3)];
            }
            bs[tid] = v;
        }
        if (tid == 0) *sflag = 0u;
    }

    // gate-thread identities + exact fp32 h_old in registers
    const int gb0 = tid >> 2, gu0 = tid & 3;
    const int tl  = tid - 128;
    const int gb1 = tl >> 2,  gu1 = tl & 3;
    float h0old = 0.f, h1old = 0.f;
    if (tid < 100)               h0old = hinit0[gb0 * HID + u0 + gu0];
    if (tid >= 128 && tid < 228) h1old = hinit1[gb1 * HID + u0 + gu1];

    // ldmatrix lane addressing (A = h, m16k16 tiles)
    uint32_t lb0, lb1;
    {
        const int t  = lane >> 3;
        const int ir = lane & 7;
        int arow = mt * 16 + (t & 1) * 8 + ir;
        if (arow > 25) arow = 25;                       // zeroed pad row
        const int acol = (t >> 1) * 8;
        const uint32_t aoff = (uint32_t)(arow * WSTR + kb + acol) * 2u;
        lb0 = smem_u32(sh0) + aoff;
        lb1 = smem_u32(sh1) + aoff;
    }
    const int wbase = (lane >> 2) * WSTR + ((lane & 3) << 1) + kb;

    const int r0 = mt ? 16 : 0;
    const int nr = mt ? 9  : 16;     // rows this warp stages

    float Dsh[2][4];                 // shadow (ih1) frags, cross-barrier
#pragma unroll
    for (int n = 0; n < 2; n++)
#pragma unroll
        for (int e = 0; e < 4; e++) Dsh[n][e] = 0.f;

    __syncthreads();

    // ---- main-tile B fragments (hi) into registers: 4 tiles x 8 ks x 2
    uint32_t Bm0[4][8], Bm1[4][8];
#pragma unroll
    for (int nt = 0; nt < 4; nt++)
#pragma unroll
        for (int ks = 0; ks < 8; ks++) {
            const int idx = wbase + ks * 16 + nt * 8 * WSTR;
            Bm0[nt][ks] = *(const uint32_t*)(whi + idx);
            Bm1[nt][ks] = *(const uint32_t*)(whi + idx + 8);
        }

    // ---- prime xg for step 0
    float xr0 = 0.f, xz0 = 0.f, xn0 = 0.f;
    if (tid < 100) {
        const float* xrow = g_xg + (size_t)gb0 * SEQT * G3 + u0 + gu0;
        xr0 = __ldcg(xrow);
        xz0 = __ldcg(xrow + HID);
        xn0 = __ldcg(xrow + 2 * HID);
    }

    for (int s = 0; s <= SEQT + 1; s++) {
        // ---- warp-local staging of h0[s-1], h1[s-3] (fp16)
        if (s == 0) {
            for (int i = lane; i < nr * 32; i += 32) {
                const int r = r0 + (i >> 5), q = i & 31;
                float4 v = __ldcg((const float4*)(hinit0 + r * HID + kb) + q);
                const int o = r * WSTR + kb + q * 4;
                sh0[o + 0] = __float2half_rn(v.x);
                sh0[o + 1] = __float2half_rn(v.y);
                sh0[o + 2] = __float2half_rn(v.z);
                sh0[o + 3] = __float2half_rn(v.w);
            }
        } else {
            const __half* s0 = g_h0[(s - 1) & 1];
            for (int i = lane; i < nr * 16; i += 32) {
                const int r = r0 + (i >> 4), q = i & 15;
                float4 vh = __ldcg((const float4*)(s0 + r * HID + kb) + q);
                *((float4*)(sh0 + r * WSTR + kb) + q) = vh;
            }
        }
        if (s <= 2) {
            for (int i = lane; i < nr * 32; i += 32) {
                const int r = r0 + (i >> 5), q = i & 31;
                float4 v = __ldcg((const float4*)(hinit1 + r * HID + kb) + q);
                const int o = r * WSTR + kb + q * 4;
                sh1[o + 0] = __float2half_rn(v.x);
                sh1[o + 1] = __float2half_rn(v.y);
                sh1[o + 2] = __float2half_rn(v.z);
                sh1[o + 3] = __float2half_rn(v.w);
            }
        } else {
            const __half* s1 = g_h1[(s - 1) & 1];
            for (int i = lane; i < nr * 16; i += 32) {
                const int r = r0 + (i >> 4), q = i & 15;
                float4 vh = __ldcg((const float4*)(s1 + r * HID + kb) + q);
                *((float4*)(sh1 + r * WSTR + kb) + q) = vh;
            }
        }
        __syncwarp();

        // ---- main MMA (critical path): tiles 0-1 (hh0.h0), 2-3 (hh1.h1),
        //      W-hi only, B from registers -> 32 HMMA, no LDS
        float D[4][4];
#pragma unroll
        for (int n = 0; n < 4; n++)
#pragma unroll
            for (int e = 0; e < 4; e++) D[n][e] = 0.f;

#pragma unroll
        for (int ks = 0; ks < 8; ks++) {
            uint32_t a0[4], a1[4];
            ldm_x4(a0, lb0 + ks * 32);
            ldm_x4(a1, lb1 + ks * 32);
#pragma unroll
            for (int nt = 0; nt < 4; nt++) {
                const uint32_t* A = (nt < 2) ? a0 : a1;
                mma_fp16(D[nt], A, Bm0[nt][ks], Bm1[nt][ks]);
            }
        }

        // ---- dump main D (tiles 0-3) + previous shadow D (tiles 4-5)
        {
            const int c2 = (lane & 3) << 1;
            const int b  = mt * 16 + (lane >> 2);
#pragma unroll
            for (int nt = 0; nt < 4; nt++) {
                const int col = nt * 8 + c2;
                ps[(kw * NROW + col    ) * PSTR + b    ] = D[nt][0];
                ps[(kw * NROW + col + 1) * PSTR + b    ] = D[nt][1];
                ps[(kw * NROW + col    ) * PSTR + b + 8] = D[nt][2];
                ps[(kw * NROW + col + 1) * PSTR + b + 8] = D[nt][3];
            }
#pragma unroll
            for (int nt = 0; nt < 2; nt++) {
                const int col = (4 + nt) * 8 + c2;
                ps[(kw * NROW + col    ) * PSTR + b    ] = Dsh[nt][0];
                ps[(kw * NROW + col + 1) * PSTR + b    ] = Dsh[nt][1];
                ps[(kw * NROW + col    ) * PSTR + b + 8] = Dsh[nt][2];
                ps[(kw * NROW + col + 1) * PSTR + b + 8] = Dsh[nt][3];
            }
        }
        __syncthreads();

        // ---- layer-0 gates: t = s (threads 0..99)
        if (tid < 100 && s < SEQT) {
            const int u = u0 + gu0;
            float gr_ = bs[gu0], gz_ = bs[4 + gu0], gn_ = bs[8 + gu0];
#pragma unroll
            for (int k = 0; k < 4; k++) {
                gr_ += ps[(k * NROW +     gu0) * PSTR + gb0];
                gz_ += ps[(k * NROW + 4 + gu0) * PSTR + gb0];
                gn_ += ps[(k * NROW + 8 + gu0) * PSTR + gb0];
            }
            const float r = fast_sig(xr0 + gr_);
            const float z = fast_sig(xz0 + gz_);
            const float n = fast_tanh(xn0 + r * gn_);
            const float hn = (1.f - z) * n + z * h0old;
            h0old = hn;
            g_h0[s & 1][gb0 * HID + u] = __float2half_rn(hn);
            if (s == SEQT - 1) g_h0f[gb0 * HID + u] = hn;
        }

        // ---- layer-1 gates: t = s-2 (threads 128..227)
        if (tid >= 128 && tid < 228 && s >= 2) {
            const int u = u0 + gu1;
            float hr  = bs[16 + gu1], hz = bs[20 + gu1], hn_ = bs[24 + gu1];
            float xr  = bs[32 + gu1], xz = bs[36 + gu1], xn  = bs[40 + gu1];
#pragma unroll
            for (int k = 0; k < 4; k++) {
                hr  += ps[(k * NROW + 16 + gu1) * PSTR + gb1];
                hz  += ps[(k * NROW + 20 + gu1) * PSTR + gb1];
                hn_ += ps[(k * NROW + 24 + gu1) * PSTR + gb1];
                xr  += ps[(k * NROW + 32 + gu1) * PSTR + gb1];
                xz  += ps[(k * NROW + 36 + gu1) * PSTR + gb1];
                xn  += ps[(k * NROW + 40 + gu1) * PSTR + gb1];
            }
            const float r = fast_sig(xr + hr);
            const float z = fast_sig(xz + hz);
            const float n = fast_tanh(xn + r * hn_);
            const float hnew = (1.f - z) * n + z * h1old;
            h1old = hnew;
            g_h1[s & 1][gb1 * HID + u] = __float2half_rn(hnew);
            if (s == SEQT + 1) g_h1f[gb1 * HID + u] = hnew;
        }
        __syncthreads();   // all h stores + ps reads done before arrive

        // ---- barrier arrive; SHADOW: ih1 MMA (hi+lo) + xg prefetch; release
        if (s < SEQT + 1) {
            if (tid == 0) red_release_add(&g_ctr, 1u);

            // shadow ih1 MMA: tiles 4-5, A = h0[s-1] (sh0 still valid)
#pragma unroll
            for (int n = 0; n < 2; n++)
#pragma unroll
                for (int e = 0; e < 4; e++) Dsh[n][e] = 0.f;
#pragma unroll
            for (int ks = 0; ks < 8; ks++) {
                uint32_t a0[4];
                ldm_x4(a0, lb0 + ks * 32);
                const int wi = wbase + ks * 16;
#pragma unroll
                for (int nt = 0; nt < 2; nt++) {
                    const int idx = wi + (4 + nt) * 8 * WSTR;
                    const uint32_t b0h = *(const uint32_t*)(whi + idx);
                    const uint32_t b1h = *(const uint32_t*)(whi + idx + 8);
                    const uint32_t b0l = *(const uint32_t*)(wlo + idx);
                    const uint32_t b1l = *(const uint32_t*)(wlo + idx + 8);
                    mma_fp16(Dsh[nt], a0, b0h, b1h);
                    mma_fp16(Dsh[nt], a0, b0l, b1l);
                }
            }

            // shadow xg prefetch for step s+1 (step-indexed, barrier-free)
            if (tid < 100 && (s + 1) < SEQT) {
                const float* xrow =
                    g_xg + ((size_t)gb0 * SEQT + (s + 1)) * G3 + u0 + gu0;
                xr0 = __ldcg(xrow);
                xz0 = __ldcg(xrow + HID);
                xn0 = __ldcg(xrow + 2 * HID);
            }

            // release: warps 0-1 poll global; others spin on smem flag
            const unsigned rel = (unsigned)(s + 1);
            if (lane == 0) {
                if (wid < 2) {
                    const unsigned tgt = rel * 128u;
                    while (lds_acquire(sflag_a) < rel) {
                        if (ld_acquire(&g_ctr) >= tgt) {
                            sts_release(sflag_a, rel);
                            break;
                        }
                    }
                } else {
                    while (lds_acquire(sflag_a) < rel) { }
                }
            }
            __syncwarp();
        }
    }

    // ---- self-reset: last block to finish zeroes the counters -------------
    if (tid == 0) {
        const unsigned old = atomicAdd(&g_done, 1u);
        if (old == 127u) {
            atomicExch(&g_ctr, 0u);
            atomicExch(&g_done, 0u);
        }
    }
}

// ---------------- finalize: sig = sigmoid(h1_final . fc_w + fc_b); pack out --
__global__ void finalize_kernel(const float* __restrict__ fc_w,
                                const float* __restrict__ fc_b,
                                float* __restrict__ out)
{
    if (blockIdx.x < 100) {
        const int idx = blockIdx.x * 256 + threadIdx.x;     // 0..25599
        const float v = (idx < BATCH * HID) ? g_h0f[idx]
                                            : g_h1f[idx - BATCH * HID];
        out[25 + idx] = v;
    } else {
        // warp-parallel dot: warp w handles batches w, w+8, w+16, w+24
        const int wid  = threadIdx.x >> 5;
        const int lane = threadIdx.x & 31;
        for (int b = wid; b < BATCH; b += 8) {
            float s = 0.f;
#pragma unroll
            for (int k = lane; k < HID; k += 32)
                s += g_h1f[b * HID + k] * fc_w[k];
#pragma unroll
            for (int off = 16; off > 0; off >>= 1)
                s += __shfl_down_sync(0xFFFFFFFFu, s, off);
            if (lane == 0)
                out[b] = 1.f / (1.f + expf(-(s + fc_b[0])));
        }
    }
}

// ---------------- launch ----------------------------------------------------
extern "C" void kernel_launch(void* const* d_in, const int* in_sizes, int n_in,
                              void* d_out, int out_size)
{
    const int*   words  = (const int*)  d_in[0];
    const float* hidden = (const float*)d_in[1];
    const float* emb    = (const float*)d_in[2];
    const float* w_ih0  = (const float*)d_in[3];
    const float* w_hh0  = (const float*)d_in[4];
    const float* b_ih0  = (const float*)d_in[5];
    const float* b_hh0  = (const float*)d_in[6];
    const float* w_ih1  = (const float*)d_in[7];
    const float* w_hh1  = (const float*)d_in[8];
    const float* b_ih1  = (const float*)d_in[9];
    const float* b_hh1  = (const float*)d_in[10];
    const float* fc_w   = (const float*)d_in[11];
    const float* fc_b   = (const float*)d_in[12];
    float* out = (float*)d_out;

    const size_t smem_bytes =
        (size_t)(2 * HROWS * WSTR + 2 * NROW * WSTR) * sizeof(__half)
        + (size_t)(4 * NROW * PSTR + NROW + 16) * sizeof(float);
    cudaFuncSetAttribute(gru_fused_kernel,
                         cudaFuncAttributeMaxDynamicSharedMemorySize,
                         (int)smem_bytes);

    // 5-launch pattern; capture idx 3 = gru_fused_kernel
    cvtA_kernel<<<MROWS, KP>>>(words, emb);                          // 0
    cvtW_kernel<<<G3, KP>>>(w_ih0);                                  // 1
    gemm_tc_kernel<<<dim3(G3 / 128, (MROWS + 127) / 128), 256>>>(    // 2
        b_ih0);
    gru_fused_kernel<<<128, 256, smem_bytes>>>(                      // 3
        w_hh0, b_hh0, w_ih1, b_ih1, w_hh1, b_hh1, hidden);
    finalize_kernel<<<101, 256>>>(fc_w, fc_b, out);                  // 4
}